// round 4
// baseline (speedup 1.0000x reference)
#include <cuda_runtime.h>
#include <math.h>

#define B_  8
#define R_  64
#define C_  16
#define D_  128
#define NP_ 2016
#define CD_ 2048      // C_*D_
#define TP_ 8         // pairs per CTA in k3/k4
#define PAD_ 20       // padded row length for transposed activation tiles (16B-aligned pairs)

// ---- scratch (static device globals: allowed; runtime alloc is not) ----
__device__ float g_kbuf[B_ * R_ * CD_];                    // 4 MB
__device__ float g_x [(size_t)B_ * NP_ * CD_];             // 132 MB
__device__ float g_q [(size_t)B_ * NP_ * CD_];             // 132 MB
__device__ float g_xg[(size_t)B_ * NP_ * CD_];             // 132 MB
__device__ float g_alpha[(size_t)B_ * NP_ * R_];           // 4 MB

// ---- packed fp32x2 helpers (sm_103a FFMA2: 2x fp32 throughput vs 3-reg FFMA) ----
__device__ __forceinline__ unsigned long long fma2(unsigned long long a,
                                                   unsigned long long b,
                                                   unsigned long long c) {
    unsigned long long r;
    asm("fma.rn.f32x2 %0, %1, %2, %3;" : "=l"(r) : "l"(a), "l"(b), "l"(c));
    return r;
}
__device__ __forceinline__ unsigned long long pack2(float x) {
    unsigned long long r;
    unsigned u = __float_as_uint(x);
    asm("mov.b64 %0, {%1, %1};" : "=l"(r) : "r"(u));
    return r;
}
__device__ __forceinline__ float lo2(unsigned long long a) { return __uint_as_float((unsigned)a); }
__device__ __forceinline__ float hi2(unsigned long long a) { return __uint_as_float((unsigned)(a >> 32)); }

// 16x128 @ 128x128 matmul core.
// sT: transposed activations in smem, sT[kk*PAD_ + c], c in [0,16).
// Thread (ch, d) computes out[cc] = sum_kk sT[kk][ch*8+cc] * W[kk*128+d].
// Activation reads are warp-broadcast LDS.128; weight reads are coalesced LDG (L1/L2-hot).
__device__ __forceinline__ void mm16(const float* sT, const float* __restrict__ W,
                                     int d, int ch, float out[8]) {
    unsigned long long a0 = 0ull, a1 = 0ull, a2 = 0ull, a3 = 0ull;
    const float* wp = W + d;
    const float* bp = sT + ch * 8;
#pragma unroll 8
    for (int kk = 0; kk < 128; ++kk) {
        unsigned long long w2 = pack2(wp[kk * D_]);
        const ulonglong2* p = (const ulonglong2*)(bp + kk * PAD_);
        ulonglong2 q0 = p[0];
        ulonglong2 q1 = p[1];
        a0 = fma2(q0.x, w2, a0);
        a1 = fma2(q0.y, w2, a1);
        a2 = fma2(q1.x, w2, a2);
        a3 = fma2(q1.y, w2, a3);
    }
    out[0] = lo2(a0); out[1] = hi2(a0);
    out[2] = lo2(a1); out[3] = hi2(a1);
    out[4] = lo2(a2); out[5] = hi2(a2);
    out[6] = lo2(a3); out[7] = hi2(a3);
}

__device__ __forceinline__ float sigmoidf_(float x) { return 1.f / (1.f + expf(-x)); }
__device__ __forceinline__ float gelu_exact(float x) {
    return 0.5f * x * (1.f + erff(x * 0.70710678118654752f));
}

// ============ K1: k = batch_input @ kW + kb ============
__global__ void __launch_bounds__(256) k1_kproj(const float* __restrict__ bi,
                                                const float* __restrict__ kW,
                                                const float* __restrict__ kb) {
    __shared__ float sT[D_ * PAD_];
    int t = threadIdx.x;
    const float* in = bi + (size_t)blockIdx.x * 16 * D_;
#pragma unroll
    for (int it = 0; it < 8; ++it) {
        int e = t + 256 * it;
        sT[(e & 127) * PAD_ + (e >> 7)] = in[e];
    }
    __syncthreads();
    int d = t & 127, ch = t >> 7;
    float out[8];
    mm16(sT, kW, d, ch, out);
    float bv = kb[d];
    float* o = g_kbuf + (size_t)blockIdx.x * 16 * D_;
#pragma unroll
    for (int cc = 0; cc < 8; ++cc) o[(ch * 8 + cc) * D_ + d] = out[cc] + bv;
}

// ============ K2: per pair: diff -> h -> z -> x -> q ============
__global__ void __launch_bounds__(256) k2_hq(const float* __restrict__ bi,
                                             const int* __restrict__ rowI,
                                             const int* __restrict__ colI,
                                             const float* __restrict__ hW,
                                             const float* __restrict__ hb,
                                             const float* __restrict__ qW,
                                             const float* __restrict__ qb) {
    __shared__ float dT[D_ * PAD_];
    __shared__ float xjT[D_ * PAD_];
    __shared__ float xT[D_ * PAD_];
    int bid = blockIdx.x;
    int b = bid / NP_, n = bid % NP_;
    int i = rowI[n], j = colI[n];
    const float* xi = bi + (size_t)(b * R_ + i) * CD_;
    const float* xj = bi + (size_t)(b * R_ + j) * CD_;
    int t = threadIdx.x;
#pragma unroll
    for (int it = 0; it < 8; ++it) {
        int e = t + 256 * it;
        int c = e >> 7, dd = e & 127;
        float a = xi[e], bb = xj[e];
        dT[dd * PAD_ + c] = a - bb;
        xjT[dd * PAD_ + c] = bb;
    }
    __syncthreads();
    int d = t & 127, ch = t >> 7;
    float hv[8];
    mm16(dT, hW, d, ch, hv);
    float hbv = hb[d];
    float* gx = g_x + ((size_t)b * NP_ + n) * CD_;
    float xv[8];
#pragma unroll
    for (int cc = 0; cc < 8; ++cc) {
        int c = ch * 8 + cc;
        float h = hv[cc] + hbv;
        float z = sigmoidf_(h);
        xv[cc] = xjT[d * PAD_ + c] + z * dT[d * PAD_ + c];   // z*xi + (1-z)*xj
    }
#pragma unroll
    for (int cc = 0; cc < 8; ++cc) {
        int c = ch * 8 + cc;
        xT[d * PAD_ + c] = xv[cc];
        gx[c * D_ + d] = xv[cc];
    }
    __syncthreads();
    float qv[8];
    mm16(xT, qW, d, ch, qv);
    float qbv = qb[d];
    float* gq = g_q + ((size_t)b * NP_ + n) * CD_;
#pragma unroll
    for (int cc = 0; cc < 8; ++cc) gq[(ch * 8 + cc) * D_ + d] = qv[cc] + qbv;
}

// ============ K3: alpha = softmax(mask(scale * q . k)) ============
__global__ void __launch_bounds__(256) k3_alpha(const int* __restrict__ rowI,
                                                const int* __restrict__ colI) {
    __shared__ float kr[2][CD_];
    __shared__ float sal[TP_][R_];
    const int tiles = NP_ / TP_;
    int b = blockIdx.x / tiles;
    int n0 = (blockIdx.x % tiles) * TP_;
    int t = threadIdx.x, p = t >> 5, lane = t & 31;
    int n = n0 + p;
    const float* qrow = g_q + ((size_t)b * NP_ + n) * CD_;
    float qreg[64];
#pragma unroll
    for (int i2 = 0; i2 < 64; ++i2) qreg[i2] = qrow[lane + 32 * i2];
    const float* kb = g_kbuf + (size_t)b * R_ * CD_;
    for (int e = t; e < CD_; e += 256) kr[0][e] = kb[e];
    __syncthreads();
    for (int r = 0; r < R_; ++r) {
        int cur = r & 1;
        if (r + 1 < R_) {
            const float* src = kb + (size_t)(r + 1) * CD_;
            for (int e = t; e < CD_; e += 256) kr[cur ^ 1][e] = src[e];
        }
        float s = 0.f;
#pragma unroll
        for (int i2 = 0; i2 < 64; ++i2) s += qreg[i2] * kr[cur][lane + 32 * i2];
#pragma unroll
        for (int off = 16; off; off >>= 1) s += __shfl_xor_sync(0xffffffffu, s, off);
        if (lane == 0) sal[p][r] = s;
        __syncthreads();
    }
    // masked softmax over 64 values per pair (warp p)
    const float scale = 0.022097086912079608f;  // 1/sqrt(D*C)
    int mi = rowI[n], mj = colI[n];
    const float NEG_INF = __int_as_float(0xff800000);
    float a0 = sal[p][lane] * scale;
    float a1 = sal[p][lane + 32] * scale;
    if (lane == mi || lane == mj) a0 = NEG_INF;
    if (lane + 32 == mi || lane + 32 == mj) a1 = NEG_INF;
    float m = fmaxf(a0, a1);
#pragma unroll
    for (int off = 16; off; off >>= 1) m = fmaxf(m, __shfl_xor_sync(0xffffffffu, m, off));
    float e0 = expf(a0 - m), e1 = expf(a1 - m);
    float ss = e0 + e1;
#pragma unroll
    for (int off = 16; off; off >>= 1) ss += __shfl_xor_sync(0xffffffffu, ss, off);
    float inv = 1.f / ss;
    float* ga = g_alpha + ((size_t)b * NP_ + n) * R_;
    ga[lane] = e0 * inv;
    ga[lane + 32] = e1 * inv;
}

// ============ K4: x_glob = alpha @ batch_input ============
__global__ void __launch_bounds__(256) k4_xglob(const float* __restrict__ bi) {
    __shared__ float br[2][CD_];
    __shared__ float sal[TP_][R_];
    const int tiles = NP_ / TP_;
    int b = blockIdx.x / tiles;
    int n0 = (blockIdx.x % tiles) * TP_;
    int t = threadIdx.x, p = t >> 5, lane = t & 31;
    int n = n0 + p;
    for (int e = t; e < TP_ * R_; e += 256)
        sal[e >> 6][e & 63] = g_alpha[((size_t)b * NP_ + n0 + (e >> 6)) * R_ + (e & 63)];
    const float* bb = bi + (size_t)b * R_ * CD_;
    for (int e = t; e < CD_; e += 256) br[0][e] = bb[e];
    __syncthreads();
    float acc[64];
#pragma unroll
    for (int i2 = 0; i2 < 64; ++i2) acc[i2] = 0.f;
    for (int r = 0; r < R_; ++r) {
        int cur = r & 1;
        if (r + 1 < R_) {
            const float* src = bb + (size_t)(r + 1) * CD_;
            for (int e = t; e < CD_; e += 256) br[cur ^ 1][e] = src[e];
        }
        float a = sal[p][r];
#pragma unroll
        for (int i2 = 0; i2 < 64; ++i2) acc[i2] += a * br[cur][lane + 32 * i2];
        __syncthreads();
    }
    float* xo = g_xg + ((size_t)b * NP_ + n) * CD_;
#pragma unroll
    for (int i2 = 0; i2 < 64; ++i2) xo[lane + 32 * i2] = acc[i2];
}

// ============ K5: g-gate -> mix -> gelu(s1) -> s2 -> masked sum ============
__global__ void __launch_bounds__(256) k5_final(const float* __restrict__ gW,
                                                const float* __restrict__ gb,
                                                const float* __restrict__ s1W,
                                                const float* __restrict__ s1b,
                                                const float* __restrict__ s2W,
                                                const float* __restrict__ s2b,
                                                const float* __restrict__ seqm,
                                                float* __restrict__ out) {
    __shared__ float gT[D_ * PAD_];
    __shared__ float red[8][8];
    __shared__ float sc[16];
    int bid = blockIdx.x;
    int b = bid / NP_, n = bid % NP_;
    const float* xg = g_xg + ((size_t)b * NP_ + n) * CD_;
    const float* x = g_x + ((size_t)b * NP_ + n) * CD_;
    int t = threadIdx.x;
#pragma unroll
    for (int it = 0; it < 8; ++it) {
        int e = t + 256 * it;
        gT[(e & 127) * PAD_ + (e >> 7)] = xg[e];
    }
    __syncthreads();
    int d = t & 127, ch = t >> 7;
    float gv[8];
    mm16(gT, gW, d, ch, gv);
    float gbv = gb[d];
    float xf[8];
#pragma unroll
    for (int cc = 0; cc < 8; ++cc) {
        int c = ch * 8 + cc;
        float g = gv[cc] + gbv;
        float w = sigmoidf_(g);
        float xgv = gT[d * PAD_ + c];
        float xv = x[c * D_ + d];
        xf[cc] = xv + w * (xgv - xv);   // (1-w)*x + w*xg
    }
    __syncthreads();  // all mm16 reads of gT done before in-place overwrite
#pragma unroll
    for (int cc = 0; cc < 8; ++cc) gT[d * PAD_ + ch * 8 + cc] = xf[cc];
    __syncthreads();
    float sv[8];
    mm16(gT, s1W, d, ch, sv);
    float s1bv = s1b[d];
    float w2v = s2W[d];
#pragma unroll
    for (int cc = 0; cc < 8; ++cc) {
        float u = sv[cc] + s1bv;
        float v = gelu_exact(u) * w2v;
#pragma unroll
        for (int off = 16; off; off >>= 1) v += __shfl_xor_sync(0xffffffffu, v, off);
        if ((t & 31) == 0) red[t >> 5][cc] = v;
    }
    __syncthreads();
    if (t < 16) {
        int c = t;
        int chh = c >> 3, cc = c & 7;
        float s = red[chh * 4 + 0][cc] + red[chh * 4 + 1][cc] +
                  red[chh * 4 + 2][cc] + red[chh * 4 + 3][cc] + s2b[0];
        sc[c] = s * seqm[b * C_ + c];
    }
    __syncthreads();
    if (t == 0) {
        float s = 0.f;
#pragma unroll
        for (int c = 0; c < 16; ++c) s += sc[c];
        out[(size_t)b * NP_ + n] = s;
    }
}

extern "C" void kernel_launch(void* const* d_in, const int* in_sizes, int n_in,
                              void* d_out, int out_size) {
    const float* bi  = (const float*)d_in[0];
    const float* seqm = (const float*)d_in[1];
    const int* rowI = (const int*)d_in[2];
    const int* colI = (const int*)d_in[3];
    const float* hW = (const float*)d_in[4];
    const float* hb = (const float*)d_in[5];
    const float* gW = (const float*)d_in[6];
    const float* gb = (const float*)d_in[7];
    const float* qW = (const float*)d_in[8];
    const float* qb = (const float*)d_in[9];
    const float* kW = (const float*)d_in[10];
    const float* kb = (const float*)d_in[11];
    const float* s1W = (const float*)d_in[12];
    const float* s1b = (const float*)d_in[13];
    const float* s2W = (const float*)d_in[14];
    const float* s2b = (const float*)d_in[15];
    float* out = (float*)d_out;

    k1_kproj<<<(B_ * R_ * C_) / 16, 256>>>(bi, kW, kb);
    k2_hq<<<B_ * NP_, 256>>>(bi, rowI, colI, hW, hb, qW, qb);
    k3_alpha<<<B_ * (NP_ / TP_), 256>>>(rowI, colI);
    k4_xglob<<<B_ * (NP_ / TP_), 256>>>(bi);
    k5_final<<<B_ * NP_, 256>>>(gW, gb, s1W, s1b, s2W, s2b, seqm, out);
}

// round 10
// speedup vs baseline: 2.0776x; 2.0776x over previous
#include <cuda_runtime.h>
#include <math.h>

#define B_  8
#define R_  64
#define C_  16
#define D_  128
#define NP_ 2016
#define CD_ 2048

// ---- scratch (static device globals) ----
__device__ float g_x [(size_t)B_ * NP_ * CD_];   // x (gated pair features)
__device__ float g_q [(size_t)B_ * NP_ * CD_];   // q projection; later reused as xf scratch in k5
__device__ float g_xg[(size_t)B_ * NP_ * CD_];   // x_glob
__device__ float g_kT[(size_t)B_ * CD_ * R_];    // k-projection, transposed [b][cd][r]
__device__ float g_aT[(size_t)B_ * R_  * NP_];   // alpha transposed [b][r][n]

// ---- packed fp32x2 helpers ----
__device__ __forceinline__ unsigned long long fma2(unsigned long long a,
                                                   unsigned long long b,
                                                   unsigned long long c) {
    unsigned long long r;
    asm("fma.rn.f32x2 %0, %1, %2, %3;" : "=l"(r) : "l"(a), "l"(b), "l"(c));
    return r;
}
__device__ __forceinline__ unsigned long long pack2(float x) {
    unsigned long long r;
    unsigned u = __float_as_uint(x);
    asm("mov.b64 %0, {%1, %1};" : "=l"(r) : "r"(u));
    return r;
}
__device__ __forceinline__ float lo2(unsigned long long a) { return __uint_as_float((unsigned)a); }
__device__ __forceinline__ float hi2(unsigned long long a) { return __uint_as_float((unsigned)(a >> 32)); }

__device__ __forceinline__ float sigmoid_fast(float x) { return 1.f / (1.f + __expf(-x)); }
__device__ __forceinline__ float gelu_exact(float x) {
    return 0.5f * x * (1.f + erff(x * 0.70710678118654752f));
}

// ================= register-tiled GEMM core =================
// As: k-major [k][i] with leading dim ALD (i contiguous).  A operands are read
// as native 64-bit (i,i+1) pairs -> no packing movs on the A side.
// Bs: k-major [k][j] with leading dim BLD.  B values packed via mov.b64 (alu pipe).
// Thread computes an 8(i) x JJ(j) tile: acc[jj][ip] is the f32x2 pair over rows
// (i0+2ip, i0+2ip+1) at column j0+jj.
template <int JJ>
__device__ __forceinline__ void mmcore(const float* As, int ALD,
                                       const float* Bs, int BLD,
                                       int i0, int j0, int K,
                                       unsigned long long acc[][4]) {
#pragma unroll 4
    for (int k = 0; k < K; ++k) {
        const ulonglong2* ap = (const ulonglong2*)(As + k * ALD + i0);
        ulonglong2 a01 = ap[0];
        ulonglong2 a23 = ap[1];
        const float4* bp = (const float4*)(Bs + k * BLD + j0);
        float bv[JJ];
        float4 b0 = bp[0];
        bv[0] = b0.x; bv[1] = b0.y; bv[2] = b0.z; bv[3] = b0.w;
        if (JJ == 8) {
            float4 b1 = bp[1];
            bv[4] = b1.x; bv[5] = b1.y; bv[6] = b1.z; bv[7] = b1.w;
        }
#pragma unroll
        for (int jj = 0; jj < JJ; ++jj) {
            unsigned long long b2 = pack2(bv[jj]);
            acc[jj][0] = fma2(a01.x, b2, acc[jj][0]);
            acc[jj][1] = fma2(a01.y, b2, acc[jj][1]);
            acc[jj][2] = fma2(a23.x, b2, acc[jj][2]);
            acc[jj][3] = fma2(a23.y, b2, acc[jj][3]);
        }
    }
}

#define ZERO_ACC(acc, JJ)                                          \
    _Pragma("unroll") for (int jj = 0; jj < JJ; ++jj)              \
        _Pragma("unroll") for (int ip = 0; ip < 4; ++ip) acc[jj][ip] = 0ull;

// smem byte sizes
#define SM1_ ((128 * 132 + 128 * 128) * 4)
#define SM2_ ((128 * 132 + 128 * 128) * 4)
#define SM3_ ((64 * 132 + 64 * 64) * 4)
#define SM4_ ((64 * 132 + 64 * 128) * 4)
#define SM5_ ((128 * 132 + 128 * 128 + 128 * 17 + 128) * 4)

// ============ K1: kT[b][cd][r] = (bi @ kW + kb)^T ============
__global__ void __launch_bounds__(256) k1_kproj(const float* __restrict__ bi,
                                                const float* __restrict__ kW,
                                                const float* __restrict__ kb) {
    extern __shared__ float sm[];
    float* As = sm;                 // [128][132] k-major
    float* Bs = sm + 128 * 132;     // [128][128]
    int tid = threadIdx.x;
    int i0 = (tid >> 4) * 8, j0 = (tid & 15) * 8;
    int lrow = tid & 127, lhalf = tid >> 7;
    int row0 = blockIdx.x * 128;
    {
        const float4* in4 = (const float4*)(bi + (size_t)(row0 + lrow) * D_);
#pragma unroll
        for (int f = 0; f < 16; ++f) {
            int d4 = lhalf * 16 + f;
            float4 v = in4[d4];
            int k = d4 * 4;
            As[(k + 0) * 132 + lrow] = v.x;
            As[(k + 1) * 132 + lrow] = v.y;
            As[(k + 2) * 132 + lrow] = v.z;
            As[(k + 3) * 132 + lrow] = v.w;
        }
        const float4* w4 = (const float4*)kW;
        float4* bs4 = (float4*)Bs;
#pragma unroll
        for (int f = 0; f < 16; ++f) bs4[tid + 256 * f] = w4[tid + 256 * f];
    }
    __syncthreads();
    unsigned long long acc[8][4];
    ZERO_ACC(acc, 8)
    mmcore<8>(As, 132, Bs, 128, i0, j0, 128, acc);
    float kbv[8];
    {
        const float4* b4 = (const float4*)(kb + j0);
        float4 t0 = b4[0], t1 = b4[1];
        kbv[0] = t0.x; kbv[1] = t0.y; kbv[2] = t0.z; kbv[3] = t0.w;
        kbv[4] = t1.x; kbv[5] = t1.y; kbv[6] = t1.z; kbv[7] = t1.w;
    }
#pragma unroll
    for (int ip = 0; ip < 4; ++ip)
#pragma unroll
        for (int s = 0; s < 2; ++s) {
            int grow = row0 + i0 + 2 * ip + s;
            int bb = grow >> 10;
            int r = (grow >> 4) & 63;
            int c = grow & 15;
            float* base = g_kT + ((size_t)bb * CD_ + c * D_ + j0) * R_ + r;
#pragma unroll
            for (int jj = 0; jj < 8; ++jj) {
                float v = (s ? hi2(acc[jj][ip]) : lo2(acc[jj][ip])) + kbv[jj];
                base[jj * R_] = v;
            }
        }
}

// ============ K2: gather diff -> h GEMM -> gate -> x -> q GEMM ============
__global__ void __launch_bounds__(256) k2_hq(const float* __restrict__ bi,
                                             const int* __restrict__ rowI,
                                             const int* __restrict__ colI,
                                             const float* __restrict__ hW,
                                             const float* __restrict__ hb,
                                             const float* __restrict__ qW,
                                             const float* __restrict__ qb) {
    extern __shared__ float sm[];
    float* As = sm;
    float* Bs = sm + 128 * 132;
    int b = blockIdx.x / 252;
    int p0 = (blockIdx.x % 252) * 8;
    int tid = threadIdx.x;
    int i0 = (tid >> 4) * 8, j0 = (tid & 15) * 8;
    int lrow = tid & 127, lhalf = tid >> 7;
    {
        int p = lrow >> 4, c = lrow & 15;
        int ri = rowI[p0 + p], rj = colI[p0 + p];
        const float4* xi4 = (const float4*)(bi + (((size_t)b * R_ + ri) * C_ + c) * D_);
        const float4* xj4 = (const float4*)(bi + (((size_t)b * R_ + rj) * C_ + c) * D_);
#pragma unroll
        for (int f = 0; f < 16; ++f) {
            int d4 = lhalf * 16 + f;
            float4 vi = xi4[d4], vj = xj4[d4];
            int k = d4 * 4;
            As[(k + 0) * 132 + lrow] = vi.x - vj.x;
            As[(k + 1) * 132 + lrow] = vi.y - vj.y;
            As[(k + 2) * 132 + lrow] = vi.z - vj.z;
            As[(k + 3) * 132 + lrow] = vi.w - vj.w;
        }
        const float4* w4 = (const float4*)hW;
        float4* bs4 = (float4*)Bs;
#pragma unroll
        for (int f = 0; f < 16; ++f) bs4[tid + 256 * f] = w4[tid + 256 * f];
    }
    __syncthreads();
    unsigned long long acc[8][4];
    ZERO_ACC(acc, 8)
    mmcore<8>(As, 132, Bs, 128, i0, j0, 128, acc);
    // ---- gating epilogue: x = xj + sigmoid(h)*(xi-xj), write to g_x ----
    {
        float hbv[8];
        const float4* h4 = (const float4*)(hb + j0);
        float4 t0 = h4[0], t1 = h4[1];
        hbv[0] = t0.x; hbv[1] = t0.y; hbv[2] = t0.z; hbv[3] = t0.w;
        hbv[4] = t1.x; hbv[5] = t1.y; hbv[6] = t1.z; hbv[7] = t1.w;
        int p = i0 >> 4;
        int ri = rowI[p0 + p], rj = colI[p0 + p];
        const float* xib = bi + ((size_t)b * R_ + ri) * C_ * D_ + j0;
        const float* xjb = bi + ((size_t)b * R_ + rj) * C_ * D_ + j0;
        float* xo = g_x + ((size_t)(b * NP_) + p0 + p) * CD_ + j0;
#pragma unroll
        for (int ip = 0; ip < 4; ++ip)
#pragma unroll
            for (int s = 0; s < 2; ++s) {
                int irow = i0 + 2 * ip + s;
                int c = irow & 15;
                const float4* xi4 = (const float4*)(xib + c * D_);
                const float4* xj4 = (const float4*)(xjb + c * D_);
                float4 vi0 = xi4[0], vi1 = xi4[1];
                float4 vj0 = xj4[0], vj1 = xj4[1];
                float xi[8] = {vi0.x, vi0.y, vi0.z, vi0.w, vi1.x, vi1.y, vi1.z, vi1.w};
                float xj[8] = {vj0.x, vj0.y, vj0.z, vj0.w, vj1.x, vj1.y, vj1.z, vj1.w};
                float ox[8];
#pragma unroll
                for (int jj = 0; jj < 8; ++jj) {
                    float h = (s ? hi2(acc[jj][ip]) : lo2(acc[jj][ip])) + hbv[jj];
                    float z = sigmoid_fast(h);
                    ox[jj] = xj[jj] + z * (xi[jj] - xj[jj]);
                }
                float4* dst = (float4*)(xo + c * D_);
                dst[0] = make_float4(ox[0], ox[1], ox[2], ox[3]);
                dst[1] = make_float4(ox[4], ox[5], ox[6], ox[7]);
            }
    }
    __syncthreads();   // x globally visible to block; As/Bs reads finished
    {
        int p = lrow >> 4, c = lrow & 15;
        const float4* x4 = (const float4*)(g_x + ((size_t)(b * NP_) + p0 + p) * CD_ + c * D_);
#pragma unroll
        for (int f = 0; f < 16; ++f) {
            int d4 = lhalf * 16 + f;
            float4 v = x4[d4];
            int k = d4 * 4;
            As[(k + 0) * 132 + lrow] = v.x;
            As[(k + 1) * 132 + lrow] = v.y;
            As[(k + 2) * 132 + lrow] = v.z;
            As[(k + 3) * 132 + lrow] = v.w;
        }
        const float4* w4 = (const float4*)qW;
        float4* bs4 = (float4*)Bs;
#pragma unroll
        for (int f = 0; f < 16; ++f) bs4[tid + 256 * f] = w4[tid + 256 * f];
    }
    __syncthreads();
    ZERO_ACC(acc, 8)
    mmcore<8>(As, 132, Bs, 128, i0, j0, 128, acc);
    {
        float qbv[8];
        const float4* b4 = (const float4*)(qb + j0);
        float4 t0 = b4[0], t1 = b4[1];
        qbv[0] = t0.x; qbv[1] = t0.y; qbv[2] = t0.z; qbv[3] = t0.w;
        qbv[4] = t1.x; qbv[5] = t1.y; qbv[6] = t1.z; qbv[7] = t1.w;
        int p = i0 >> 4;
        float* qo = g_q + ((size_t)(b * NP_) + p0 + p) * CD_ + j0;
#pragma unroll
        for (int ip = 0; ip < 4; ++ip)
#pragma unroll
            for (int s = 0; s < 2; ++s) {
                int irow = i0 + 2 * ip + s;
                int c = irow & 15;
                float o[8];
#pragma unroll
                for (int jj = 0; jj < 8; ++jj)
                    o[jj] = (s ? hi2(acc[jj][ip]) : lo2(acc[jj][ip])) + qbv[jj];
                float4* dst = (float4*)(qo + c * D_);
                dst[0] = make_float4(o[0], o[1], o[2], o[3]);
                dst[1] = make_float4(o[4], o[5], o[6], o[7]);
            }
    }
}

// ============ K3: alpha^T = softmax(mask(scale * q @ kT)) ============
__global__ void __launch_bounds__(256) k3_alpha(const int* __restrict__ rowI,
                                                const int* __restrict__ colI) {
    extern __shared__ float sm[];
    float* As = sm;               // [64][132]
    float* Bs = sm + 64 * 132;    // [64][64]
    float* L = sm;                // overlay after GEMM: [64][129]
    int b = blockIdx.x >> 4;
    int n0 = (blockIdx.x & 15) * 128;
    int tid = threadIdx.x;
    int i0 = (tid >> 4) * 8, j0 = (tid & 15) * 4;
    int lrow = tid & 127, lhalf = tid >> 7;
    int nr = n0 + lrow;
    if (nr > NP_ - 1) nr = NP_ - 1;
    const float4* q4 = (const float4*)(g_q + (size_t)(b * NP_ + nr) * CD_);
    unsigned long long acc[4][4];
    ZERO_ACC(acc, 4)
    for (int k0 = 0; k0 < CD_; k0 += 64) {
        __syncthreads();
#pragma unroll
        for (int f = 0; f < 8; ++f) {
            int d4 = lhalf * 8 + f;
            float4 v = q4[(k0 >> 2) + d4];
            int k = d4 * 4;
            As[(k + 0) * 132 + lrow] = v.x;
            As[(k + 1) * 132 + lrow] = v.y;
            As[(k + 2) * 132 + lrow] = v.z;
            As[(k + 3) * 132 + lrow] = v.w;
        }
        {
            // FIXED: the 64-row K-chunk of kT is one contiguous 4096-float span.
            // Load the full [64][64] Bs tile (1024 float4) with 4 coalesced
            // float4 copies per thread.  (Previous version loaded only 1/4 of
            // the tile -> stale smem in the logits -> rel_err 3.4e-2.)
            const float4* src = (const float4*)(g_kT + ((size_t)b * CD_ + k0) * R_);
            float4* dst = (float4*)Bs;
            dst[tid]       = src[tid];
            dst[tid + 256] = src[tid + 256];
            dst[tid + 512] = src[tid + 512];
            dst[tid + 768] = src[tid + 768];
        }
        __syncthreads();
        mmcore<4>(As, 132, Bs, 64, i0, j0, 64, acc);
    }
    __syncthreads();
#pragma unroll
    for (int jj = 0; jj < 4; ++jj)
#pragma unroll
        for (int ip = 0; ip < 4; ++ip) {
            L[(j0 + jj) * 129 + (i0 + 2 * ip)]     = lo2(acc[jj][ip]);
            L[(j0 + jj) * 129 + (i0 + 2 * ip + 1)] = hi2(acc[jj][ip]);
        }
    __syncthreads();
    if (tid < 128) {
        const float scale = 0.022097086912079608f;   // 1/sqrt(D*C)
        const float NEG_INF = __int_as_float(0xff800000);
        int n = n0 + tid;
        int nc = (n > NP_ - 1) ? NP_ - 1 : n;
        int mi = rowI[nc], mj = colI[nc];
        float m = NEG_INF;
#pragma unroll 8
        for (int r = 0; r < 64; ++r) {
            float v = L[r * 129 + tid] * scale;
            if (r == mi || r == mj) v = NEG_INF;
            m = fmaxf(m, v);
        }
        float ssum = 0.f;
#pragma unroll 8
        for (int r = 0; r < 64; ++r) {
            float v = L[r * 129 + tid] * scale;
            if (r == mi || r == mj) v = NEG_INF;
            float e = __expf(v - m);
            ssum += e;
            L[r * 129 + tid] = e;
        }
        float inv = 1.f / ssum;
        if (n < NP_) {
            float* dst = g_aT + (size_t)b * R_ * NP_ + n;
#pragma unroll 8
            for (int r = 0; r < 64; ++r) dst[(size_t)r * NP_] = L[r * 129 + tid] * inv;
        }
    }
}

// ============ K4: x_glob = alpha @ batch_input ============
__global__ void __launch_bounds__(256) k4_xglob(const float* __restrict__ bi) {
    extern __shared__ float sm[];
    float* As = sm;               // [64][132]
    float* Bs = sm + 64 * 132;    // [64][128]
    int b = blockIdx.x >> 8;
    int rest = blockIdx.x & 255;
    int n0 = (rest >> 4) * 128;
    int cd0 = (rest & 15) * 128;
    int tid = threadIdx.x;
    int i0 = (tid >> 4) * 8, j0 = (tid & 15) * 8;
    {
        int row = tid & 63, part = tid >> 6;
        const float* arow = g_aT + ((size_t)b * R_ + row) * NP_;
#pragma unroll
        for (int f = 0; f < 8; ++f) {
            int col = (part * 8 + f) * 4;
            int srcc = n0 + col;
            if (srcc > NP_ - 4) srcc = NP_ - 4;
            float4 v = *(const float4*)(arow + srcc);
            *(float4*)(As + row * 132 + col) = v;
        }
        const float4* brow = (const float4*)(bi + ((size_t)b * R_ + row) * CD_ + cd0);
        float4* bsr = (float4*)(Bs + row * 128);
#pragma unroll
        for (int f = 0; f < 8; ++f) bsr[part * 8 + f] = brow[part * 8 + f];
    }
    __syncthreads();
    unsigned long long acc[8][4];
    ZERO_ACC(acc, 8)
    mmcore<8>(As, 132, Bs, 128, i0, j0, 64, acc);
#pragma unroll
    for (int ip = 0; ip < 4; ++ip)
#pragma unroll
        for (int s = 0; s < 2; ++s) {
            int n = n0 + i0 + 2 * ip + s;
            if (n < NP_) {
                float o[8];
#pragma unroll
                for (int jj = 0; jj < 8; ++jj)
                    o[jj] = s ? hi2(acc[jj][ip]) : lo2(acc[jj][ip]);
                float4* dst = (float4*)(g_xg + ((size_t)(b * NP_) + n) * CD_ + cd0 + j0);
                dst[0] = make_float4(o[0], o[1], o[2], o[3]);
                dst[1] = make_float4(o[4], o[5], o[6], o[7]);
            }
        }
}

// ============ K5: g GEMM -> gate mix -> s1 GEMM -> gelu -> s2 -> masked sum ============
__global__ void __launch_bounds__(256) k5_final(const float* __restrict__ gW,
                                                const float* __restrict__ gb,
                                                const float* __restrict__ s1W,
                                                const float* __restrict__ s1b,
                                                const float* __restrict__ s2W,
                                                const float* __restrict__ s2b,
                                                const float* __restrict__ seqm,
                                                float* __restrict__ out) {
    extern __shared__ float sm[];
    float* As = sm;
    float* Bs = sm + 128 * 132;
    float* red = sm + 128 * 132 + 128 * 128;   // [128][17]
    float* srow = red + 128 * 17;              // [128]
    int b = blockIdx.x / 252;
    int p0 = (blockIdx.x % 252) * 8;
    int tid = threadIdx.x;
    int i0 = (tid >> 4) * 8, j0 = (tid & 15) * 8;
    int lrow = tid & 127, lhalf = tid >> 7;
    {
        int p = lrow >> 4, c = lrow & 15;
        const float4* xg4 = (const float4*)(g_xg + ((size_t)(b * NP_) + p0 + p) * CD_ + c * D_);
#pragma unroll
        for (int f = 0; f < 16; ++f) {
            int d4 = lhalf * 16 + f;
            float4 v = xg4[d4];
            int k = d4 * 4;
            As[(k + 0) * 132 + lrow] = v.x;
            As[(k + 1) * 132 + lrow] = v.y;
            As[(k + 2) * 132 + lrow] = v.z;
            As[(k + 3) * 132 + lrow] = v.w;
        }
        const float4* w4 = (const float4*)gW;
        float4* bs4 = (float4*)Bs;
#pragma unroll
        for (int f = 0; f < 16; ++f) bs4[tid + 256 * f] = w4[tid + 256 * f];
    }
    __syncthreads();
    unsigned long long acc[8][4];
    ZERO_ACC(acc, 8)
    mmcore<8>(As, 132, Bs, 128, i0, j0, 128, acc);
    // ---- gate mix: xf = x + sigmoid(g)*(xg - x); stash in g_q (scratch) ----
    {
        float gbv[8];
        const float4* b4 = (const float4*)(gb + j0);
        float4 t0 = b4[0], t1 = b4[1];
        gbv[0] = t0.x; gbv[1] = t0.y; gbv[2] = t0.z; gbv[3] = t0.w;
        gbv[4] = t1.x; gbv[5] = t1.y; gbv[6] = t1.z; gbv[7] = t1.w;
        int p = i0 >> 4;
        const float* xb = g_x + ((size_t)(b * NP_) + p0 + p) * CD_ + j0;
        const float* xgb = g_xg + ((size_t)(b * NP_) + p0 + p) * CD_ + j0;
        float* fo = g_q + ((size_t)(b * NP_) + p0 + p) * CD_ + j0;
#pragma unroll
        for (int ip = 0; ip < 4; ++ip)
#pragma unroll
            for (int s = 0; s < 2; ++s) {
                int irow = i0 + 2 * ip + s;
                int c = irow & 15;
                const float4* x4 = (const float4*)(xb + c * D_);
                const float4* xg4 = (const float4*)(xgb + c * D_);
                float4 vx0 = x4[0], vx1 = x4[1];
                float4 vg0 = xg4[0], vg1 = xg4[1];
                float xv[8] = {vx0.x, vx0.y, vx0.z, vx0.w, vx1.x, vx1.y, vx1.z, vx1.w};
                float gv[8] = {vg0.x, vg0.y, vg0.z, vg0.w, vg1.x, vg1.y, vg1.z, vg1.w};
                float ox[8];
#pragma unroll
                for (int jj = 0; jj < 8; ++jj) {
                    float g = (s ? hi2(acc[jj][ip]) : lo2(acc[jj][ip])) + gbv[jj];
                    float w = sigmoid_fast(g);
                    ox[jj] = xv[jj] + w * (gv[jj] - xv[jj]);
                }
                float4* dst = (float4*)(fo + c * D_);
                dst[0] = make_float4(ox[0], ox[1], ox[2], ox[3]);
                dst[1] = make_float4(ox[4], ox[5], ox[6], ox[7]);
            }
    }
    __syncthreads();
    {
        int p = lrow >> 4, c = lrow & 15;
        const float4* f4 = (const float4*)(g_q + ((size_t)(b * NP_) + p0 + p) * CD_ + c * D_);
#pragma unroll
        for (int f = 0; f < 16; ++f) {
            int d4 = lhalf * 16 + f;
            float4 v = f4[d4];
            int k = d4 * 4;
            As[(k + 0) * 132 + lrow] = v.x;
            As[(k + 1) * 132 + lrow] = v.y;
            As[(k + 2) * 132 + lrow] = v.z;
            As[(k + 3) * 132 + lrow] = v.w;
        }
        const float4* w4 = (const float4*)s1W;
        float4* bs4 = (float4*)Bs;
#pragma unroll
        for (int f = 0; f < 16; ++f) bs4[tid + 256 * f] = w4[tid + 256 * f];
    }
    __syncthreads();
    ZERO_ACC(acc, 8)
    mmcore<8>(As, 132, Bs, 128, i0, j0, 128, acc);
    {
        float s1v[8], w2[8];
        const float4* b4 = (const float4*)(s1b + j0);
        float4 t0 = b4[0], t1 = b4[1];
        s1v[0] = t0.x; s1v[1] = t0.y; s1v[2] = t0.z; s1v[3] = t0.w;
        s1v[4] = t1.x; s1v[5] = t1.y; s1v[6] = t1.z; s1v[7] = t1.w;
        const float4* w4 = (const float4*)(s2W + j0);
        float4 u0 = w4[0], u1 = w4[1];
        w2[0] = u0.x; w2[1] = u0.y; w2[2] = u0.z; w2[3] = u0.w;
        w2[4] = u1.x; w2[5] = u1.y; w2[6] = u1.z; w2[7] = u1.w;
        int tx = tid & 15;
#pragma unroll
        for (int ip = 0; ip < 4; ++ip)
#pragma unroll
            for (int s = 0; s < 2; ++s) {
                int irow = i0 + 2 * ip + s;
                float pr = 0.f;
#pragma unroll
                for (int jj = 0; jj < 8; ++jj) {
                    float u = (s ? hi2(acc[jj][ip]) : lo2(acc[jj][ip])) + s1v[jj];
                    pr += gelu_exact(u) * w2[jj];
                }
                red[irow * 17 + tx] = pr;
            }
    }
    __syncthreads();
    if (tid < 128) {
        float ssum = 0.f;
#pragma unroll
        for (int t = 0; t < 16; ++t) ssum += red[tid * 17 + t];
        ssum += s2b[0];
        ssum *= seqm[b * C_ + (tid & 15)];
        srow[tid] = ssum;
    }
    __syncthreads();
    if (tid < 8) {
        float s = 0.f;
#pragma unroll
        for (int c = 0; c < 16; ++c) s += srow[tid * 16 + c];
        out[(size_t)b * NP_ + p0 + tid] = s;
    }
}

extern "C" void kernel_launch(void* const* d_in, const int* in_sizes, int n_in,
                              void* d_out, int out_size) {
    const float* bi   = (const float*)d_in[0];
    const float* seqm = (const float*)d_in[1];
    const int* rowI   = (const int*)d_in[2];
    const int* colI   = (const int*)d_in[3];
    const float* hW = (const float*)d_in[4];
    const float* hb = (const float*)d_in[5];
    const float* gW = (const float*)d_in[6];
    const float* gb = (const float*)d_in[7];
    const float* qW = (const float*)d_in[8];
    const float* qb = (const float*)d_in[9];
    const float* kW = (const float*)d_in[10];
    const float* kb = (const float*)d_in[11];
    const float* s1W = (const float*)d_in[12];
    const float* s1b = (const float*)d_in[13];
    const float* s2W = (const float*)d_in[14];
    const float* s2b = (const float*)d_in[15];
    float* out = (float*)d_out;

    cudaFuncSetAttribute(k1_kproj, cudaFuncAttributeMaxDynamicSharedMemorySize, SM1_);
    cudaFuncSetAttribute(k2_hq,    cudaFuncAttributeMaxDynamicSharedMemorySize, SM2_);
    cudaFuncSetAttribute(k3_alpha, cudaFuncAttributeMaxDynamicSharedMemorySize, SM3_);
    cudaFuncSetAttribute(k4_xglob, cudaFuncAttributeMaxDynamicSharedMemorySize, SM4_);
    cudaFuncSetAttribute(k5_final, cudaFuncAttributeMaxDynamicSharedMemorySize, SM5_);

    k1_kproj<<<64, 256, SM1_>>>(bi, kW, kb);
    k2_hq<<<2016, 256, SM2_>>>(bi, rowI, colI, hW, hb, qW, qb);
    k3_alpha<<<128, 256, SM3_>>>(rowI, colI);
    k4_xglob<<<2048, 256, SM4_>>>(bi);
    k5_final<<<2016, 256, SM5_>>>(gW, gb, s1W, s1b, s2W, s2b, seqm, out);
}

// round 15
// speedup vs baseline: 2.6836x; 1.2917x over previous
#include <cuda_runtime.h>
#include <cuda_bf16.h>
#include <stdint.h>
#include <cstdint>
#include <math.h>

#define B_  8
#define R_  64
#define C_  16
#define D_  128
#define NP_ 2016
#define CD_ 2048

// ---- scratch (static device globals) ----
__device__ float g_x [(size_t)B_ * NP_ * CD_];   // x (gated pair features)
__device__ float g_q [(size_t)B_ * NP_ * CD_];   // q projection
__device__ float g_xg[(size_t)B_ * NP_ * CD_];   // x_glob
__device__ float g_kT[(size_t)B_ * CD_ * R_];    // k-projection, transposed [b][cd][r]
__device__ float g_aT[(size_t)B_ * R_  * NP_];   // alpha transposed [b][r][n]
// bf16 weight images row-major [n][k] (hi/lo): [0]=hW [1]=qW [2]=gW [3]=s1W
__device__ uint4 g_wh[4][2048];
__device__ uint4 g_wl[4][2048];

// ---- packed fp32x2 helpers (SIMT kernels) ----
__device__ __forceinline__ unsigned long long fma2(unsigned long long a,
                                                   unsigned long long b,
                                                   unsigned long long c) {
    unsigned long long r;
    asm("fma.rn.f32x2 %0, %1, %2, %3;" : "=l"(r) : "l"(a), "l"(b), "l"(c));
    return r;
}
__device__ __forceinline__ unsigned long long pack2(float x) {
    unsigned long long r;
    unsigned u = __float_as_uint(x);
    asm("mov.b64 %0, {%1, %1};" : "=l"(r) : "r"(u));
    return r;
}
__device__ __forceinline__ float lo2(unsigned long long a) { return __uint_as_float((unsigned)a); }
__device__ __forceinline__ float hi2(unsigned long long a) { return __uint_as_float((unsigned)(a >> 32)); }

__device__ __forceinline__ float sigmoid_fast(float x) { return 1.f / (1.f + __expf(-x)); }
__device__ __forceinline__ float gelu_exact(float x) {
    return 0.5f * x * (1.f + erff(x * 0.70710678118654752f));
}

// ================= SIMT register-tiled GEMM core (k1/k3/k4) =================
template <int JJ>
__device__ __forceinline__ void mmcore(const float* As, int ALD,
                                       const float* Bs, int BLD,
                                       int i0, int j0, int K,
                                       unsigned long long acc[][4]) {
#pragma unroll 4
    for (int k = 0; k < K; ++k) {
        const ulonglong2* ap = (const ulonglong2*)(As + k * ALD + i0);
        ulonglong2 a01 = ap[0];
        ulonglong2 a23 = ap[1];
        const float4* bp = (const float4*)(Bs + k * BLD + j0);
        float bv[JJ];
        float4 b0 = bp[0];
        bv[0] = b0.x; bv[1] = b0.y; bv[2] = b0.z; bv[3] = b0.w;
        if (JJ == 8) {
            float4 b1 = bp[1];
            bv[4] = b1.x; bv[5] = b1.y; bv[6] = b1.z; bv[7] = b1.w;
        }
#pragma unroll
        for (int jj = 0; jj < JJ; ++jj) {
            unsigned long long b2 = pack2(bv[jj]);
            acc[jj][0] = fma2(a01.x, b2, acc[jj][0]);
            acc[jj][1] = fma2(a01.y, b2, acc[jj][1]);
            acc[jj][2] = fma2(a23.x, b2, acc[jj][2]);
            acc[jj][3] = fma2(a23.y, b2, acc[jj][3]);
        }
    }
}

#define ZERO_ACC(acc, JJ)                                          \
    _Pragma("unroll") for (int jj = 0; jj < JJ; ++jj)              \
        _Pragma("unroll") for (int ip = 0; ip < 4; ++ip) acc[jj][ip] = 0ull;

#define SM1_ ((128 * 132 + 128 * 128) * 4)
#define SM3_ ((64 * 132 + 64 * 64) * 4)
#define SM4_ ((64 * 132 + 64 * 128) * 4)

// ================= HMMA (mma.sync) infrastructure for k2/k5 =================
__device__ __forceinline__ uint32_t smem_u32(const void* p) {
    uint32_t a;
    asm("{ .reg .u64 t; cvta.to.shared.u64 t, %1; cvt.u32.u64 %0, t; }" : "=r"(a) : "l"(p));
    return a;
}
__device__ __forceinline__ void ldm4(uint32_t addr, unsigned r[4]) {
    asm volatile("ldmatrix.sync.aligned.m8n8.x4.shared.b16 {%0,%1,%2,%3}, [%4];"
        : "=r"(r[0]), "=r"(r[1]), "=r"(r[2]), "=r"(r[3]) : "r"(addr));
}
__device__ __forceinline__ void mma16816(float c[4], const unsigned a[4],
                                         unsigned b0, unsigned b1) {
    asm volatile("mma.sync.aligned.m16n8k16.row.col.f32.bf16.bf16.f32 "
        "{%0,%1,%2,%3}, {%4,%5,%6,%7}, {%8,%9}, {%0,%1,%2,%3};"
        : "+f"(c[0]), "+f"(c[1]), "+f"(c[2]), "+f"(c[3])
        : "r"(a[0]), "r"(a[1]), "r"(a[2]), "r"(a[3]), "r"(b0), "r"(b1));
}

// fp32 -> (hi,lo) bf16x2 split for two values
__device__ __forceinline__ void split2(float a, float b, unsigned& h, unsigned& l) {
    __nv_bfloat162 hv = __floats2bfloat162_rn(a, b);
    float2 hf = __bfloat1622float2(hv);
    __nv_bfloat162 lv = __floats2bfloat162_rn(a - hf.x, b - hf.y);
    h = *reinterpret_cast<unsigned*>(&hv);
    l = *reinterpret_cast<unsigned*>(&lv);
}

// smem image layout: 128 rows x 272B stride (256B data + 16B pad; conflict-free ldmatrix)
#define ASTR 272
#define IMG_ (128 * ASTR)
#define A_HI 0
#define A_LO IMG_
#define W_HI (2 * IMG_)
#define W_LO (3 * IMG_)
#define HSM_ (4 * IMG_)

// 3-term split HMMA GEMM: c[mt][nt][4] += Ahi*Whi + Ahi*Wlo + Alo*Whi
// A images at aHi/aLo, W images at wHi/wLo (smem u32 addresses).
__device__ __forceinline__ void gemm_hmma(uint32_t sbase, int mbase, int nbase,
                                          int lane, float c[2][8][4]) {
#pragma unroll
    for (int mt = 0; mt < 2; ++mt)
#pragma unroll
        for (int nt = 0; nt < 8; ++nt)
#pragma unroll
            for (int i = 0; i < 4; ++i) c[mt][nt][i] = 0.f;
    int lrow = lane & 15, lhi = (lane >> 4) * 16;
#pragma unroll
    for (int kc = 0; kc < 8; ++kc) {
        unsigned ah[2][4], al[2][4];
#pragma unroll
        for (int mt = 0; mt < 2; ++mt) {
            uint32_t ra = sbase + (mbase + mt * 16 + lrow) * ASTR + kc * 32 + lhi;
            ldm4(ra + A_HI, ah[mt]);
            ldm4(ra + A_LO, al[mt]);
        }
        unsigned bh[4][4], bl[4][4];
#pragma unroll
        for (int np = 0; np < 4; ++np) {
            uint32_t rb = sbase + (nbase + np * 16 + lrow) * ASTR + kc * 32 + lhi;
            ldm4(rb + W_HI, bh[np]);
            ldm4(rb + W_LO, bl[np]);
        }
#pragma unroll
        for (int mt = 0; mt < 2; ++mt)
#pragma unroll
            for (int np = 0; np < 4; ++np) {
                mma16816(c[mt][2 * np],     ah[mt], bh[np][0], bh[np][2]);
                mma16816(c[mt][2 * np + 1], ah[mt], bh[np][1], bh[np][3]);
                mma16816(c[mt][2 * np],     ah[mt], bl[np][0], bl[np][2]);
                mma16816(c[mt][2 * np + 1], ah[mt], bl[np][1], bl[np][3]);
                mma16816(c[mt][2 * np],     al[mt], bh[np][0], bh[np][2]);
                mma16816(c[mt][2 * np + 1], al[mt], bh[np][1], bh[np][3]);
            }
    }
}

// copy one weight image pair (hi/lo) global -> smem, all 256 threads
__device__ __forceinline__ void wcopy(char* smem, int w, int tid) {
    const uint4* sh = g_wh[w];
    const uint4* sl = g_wl[w];
    for (int i = tid; i < 2048; i += 256) {
        int row = i >> 4, seg = i & 15;
        *(uint4*)(smem + W_HI + row * ASTR + seg * 16) = sh[i];
        *(uint4*)(smem + W_LO + row * ASTR + seg * 16) = sl[i];
    }
}

// ============ W prep: bf16 hi/lo weight images, row-major [n][k] ============
__global__ void __launch_bounds__(256) wprep(const float* __restrict__ hW,
                                             const float* __restrict__ qW,
                                             const float* __restrict__ gW,
                                             const float* __restrict__ s1W) {
    const float* Ws[4] = {hW, qW, gW, s1W};
    int w = blockIdx.x;
    const float* W = Ws[w];
    char* dh = (char*)&g_wh[w][0];
    char* dl = (char*)&g_wl[w][0];
    for (int e = threadIdx.x; e < 16384; e += blockDim.x) {
        int n = e >> 7, k = e & 127;
        float v = W[k * 128 + n];
        __nv_bfloat16 h = __float2bfloat16(v);
        float r = v - __bfloat162float(h);
        __nv_bfloat16 l = __float2bfloat16(r);
        *(__nv_bfloat16*)(dh + n * 256 + k * 2) = h;
        *(__nv_bfloat16*)(dl + n * 256 + k * 2) = l;
    }
}

// ============ K1: kT[b][cd][r] = (bi @ kW + kb)^T  (SIMT) ============
__global__ void __launch_bounds__(256) k1_kproj(const float* __restrict__ bi,
                                                const float* __restrict__ kW,
                                                const float* __restrict__ kb) {
    extern __shared__ float sm[];
    float* As = sm;
    float* Bs = sm + 128 * 132;
    int tid = threadIdx.x;
    int i0 = (tid >> 4) * 8, j0 = (tid & 15) * 8;
    int lrow = tid & 127, lhalf = tid >> 7;
    int row0 = blockIdx.x * 128;
    {
        const float4* in4 = (const float4*)(bi + (size_t)(row0 + lrow) * D_);
#pragma unroll
        for (int f = 0; f < 16; ++f) {
            int d4 = lhalf * 16 + f;
            float4 v = in4[d4];
            int k = d4 * 4;
            As[(k + 0) * 132 + lrow] = v.x;
            As[(k + 1) * 132 + lrow] = v.y;
            As[(k + 2) * 132 + lrow] = v.z;
            As[(k + 3) * 132 + lrow] = v.w;
        }
        const float4* w4 = (const float4*)kW;
        float4* bs4 = (float4*)Bs;
#pragma unroll
        for (int f = 0; f < 16; ++f) bs4[tid + 256 * f] = w4[tid + 256 * f];
    }
    __syncthreads();
    unsigned long long acc[8][4];
    ZERO_ACC(acc, 8)
    mmcore<8>(As, 132, Bs, 128, i0, j0, 128, acc);
    float kbv[8];
    {
        const float4* b4 = (const float4*)(kb + j0);
        float4 t0 = b4[0], t1 = b4[1];
        kbv[0] = t0.x; kbv[1] = t0.y; kbv[2] = t0.z; kbv[3] = t0.w;
        kbv[4] = t1.x; kbv[5] = t1.y; kbv[6] = t1.z; kbv[7] = t1.w;
    }
#pragma unroll
    for (int ip = 0; ip < 4; ++ip)
#pragma unroll
        for (int s = 0; s < 2; ++s) {
            int grow = row0 + i0 + 2 * ip + s;
            int bb = grow >> 10;
            int r = (grow >> 4) & 63;
            int c = grow & 15;
            float* base = g_kT + ((size_t)bb * CD_ + c * D_ + j0) * R_ + r;
#pragma unroll
            for (int jj = 0; jj < 8; ++jj) {
                float v = (s ? hi2(acc[jj][ip]) : lo2(acc[jj][ip])) + kbv[jj];
                base[jj * R_] = v;
            }
        }
}

// ============ K2 (HMMA): diff -> hGEMM -> gate -> x -> qGEMM ============
__global__ void __launch_bounds__(256) k2_mma(const float* __restrict__ bi,
                                              const int* __restrict__ rowI,
                                              const int* __restrict__ colI,
                                              const float* __restrict__ hb,
                                              const float* __restrict__ qb) {
    extern __shared__ __align__(16) char smem[];
    uint32_t sbase = smem_u32(smem);
    int tid = threadIdx.x, wid = tid >> 5, lane = tid & 31;
    int b = blockIdx.x / 252, p0 = (blockIdx.x % 252) * 8;
    int mbase = (wid & 3) * 32, nbase = (wid >> 2) * 64;

    wcopy(smem, 0, tid);   // hW
    // A = xi - xj, split -> hi/lo images
    {
        int row = tid >> 1, half = tid & 1;
        int p = row >> 4, c = row & 15;
        int ri = rowI[p0 + p], rj = colI[p0 + p];
        const float4* xi4 = (const float4*)(bi + (((size_t)b * R_ + ri) * C_ + c) * D_ + half * 64);
        const float4* xj4 = (const float4*)(bi + (((size_t)b * R_ + rj) * C_ + c) * D_ + half * 64);
        char* arow = smem + row * ASTR + half * 128;
#pragma unroll
        for (int g = 0; g < 8; ++g) {
            float4 a0 = xi4[2 * g], a1 = xi4[2 * g + 1];
            float4 b0 = xj4[2 * g], b1 = xj4[2 * g + 1];
            uint4 h4, l4;
            split2(a0.x - b0.x, a0.y - b0.y, h4.x, l4.x);
            split2(a0.z - b0.z, a0.w - b0.w, h4.y, l4.y);
            split2(a1.x - b1.x, a1.y - b1.y, h4.z, l4.z);
            split2(a1.z - b1.z, a1.w - b1.w, h4.w, l4.w);
            *(uint4*)(arow + A_HI + g * 16) = h4;
            *(uint4*)(arow + A_LO + g * 16) = l4;
        }
    }
    __syncthreads();
    float c[2][8][4];
    gemm_hmma(sbase, mbase, nbase, lane, c);
    __syncthreads();   // all warps done reading A/W before overwrite
    // epilogue 1: x = xj + sigmoid(h+hb)*(xi-xj); store g_x + rebuild A images
#pragma unroll
    for (int mt = 0; mt < 2; ++mt)
#pragma unroll
        for (int ro = 0; ro < 2; ++ro) {
            int row = mbase + mt * 16 + ro * 8 + (lane >> 2);
            int p = row >> 4, cc = row & 15, n = p0 + p;
            int ri = rowI[n], rj = colI[n];
            const float* xib = bi + (((size_t)b * R_ + ri) * C_ + cc) * D_;
            const float* xjb = bi + (((size_t)b * R_ + rj) * C_ + cc) * D_;
            float* xo = g_x + ((size_t)(b * NP_) + n) * CD_ + cc * D_;
            char* arow = smem + row * ASTR;
#pragma unroll
            for (int nt = 0; nt < 8; ++nt) {
                int col = nbase + nt * 8 + (lane & 3) * 2;
                float2 vi = *(const float2*)(xib + col);
                float2 vj = *(const float2*)(xjb + col);
                float2 hbv = *(const float2*)(hb + col);
                float h0 = c[mt][nt][ro * 2 + 0] + hbv.x;
                float h1 = c[mt][nt][ro * 2 + 1] + hbv.y;
                float x0 = vj.x + sigmoid_fast(h0) * (vi.x - vj.x);
                float x1 = vj.y + sigmoid_fast(h1) * (vi.y - vj.y);
                *(float2*)(xo + col) = make_float2(x0, x1);
                unsigned hreg, lreg;
                split2(x0, x1, hreg, lreg);
                *(unsigned*)(arow + A_HI + col * 2) = hreg;
                *(unsigned*)(arow + A_LO + col * 2) = lreg;
            }
        }
    wcopy(smem, 1, tid);   // qW
    __syncthreads();
    gemm_hmma(sbase, mbase, nbase, lane, c);
    // epilogue 2: q = c + qb -> g_q
#pragma unroll
    for (int mt = 0; mt < 2; ++mt)
#pragma unroll
        for (int ro = 0; ro < 2; ++ro) {
            int row = mbase + mt * 16 + ro * 8 + (lane >> 2);
            int p = row >> 4, cc = row & 15;
            float* qo = g_q + ((size_t)(b * NP_) + p0 + p) * CD_ + cc * D_;
#pragma unroll
            for (int nt = 0; nt < 8; ++nt) {
                int col = nbase + nt * 8 + (lane & 3) * 2;
                float2 qbv = *(const float2*)(qb + col);
                *(float2*)(qo + col) = make_float2(c[mt][nt][ro * 2 + 0] + qbv.x,
                                                   c[mt][nt][ro * 2 + 1] + qbv.y);
            }
        }
}

// ============ K3: alpha^T = softmax(mask(scale * q @ kT))  (SIMT) ============
__global__ void __launch_bounds__(256) k3_alpha(const int* __restrict__ rowI,
                                                const int* __restrict__ colI) {
    extern __shared__ float sm[];
    float* As = sm;
    float* Bs = sm + 64 * 132;
    float* L = sm;
    int b = blockIdx.x >> 4;
    int n0 = (blockIdx.x & 15) * 128;
    int tid = threadIdx.x;
    int i0 = (tid >> 4) * 8, j0 = (tid & 15) * 4;
    int lrow = tid & 127, lhalf = tid >> 7;
    int nr = n0 + lrow;
    if (nr > NP_ - 1) nr = NP_ - 1;
    const float4* q4 = (const float4*)(g_q + (size_t)(b * NP_ + nr) * CD_);
    unsigned long long acc[4][4];
    ZERO_ACC(acc, 4)
    for (int k0 = 0; k0 < CD_; k0 += 64) {
        __syncthreads();
#pragma unroll
        for (int f = 0; f < 8; ++f) {
            int d4 = lhalf * 8 + f;
            float4 v = q4[(k0 >> 2) + d4];
            int k = d4 * 4;
            As[(k + 0) * 132 + lrow] = v.x;
            As[(k + 1) * 132 + lrow] = v.y;
            As[(k + 2) * 132 + lrow] = v.z;
            As[(k + 3) * 132 + lrow] = v.w;
        }
        {
            const float4* src = (const float4*)(g_kT + ((size_t)b * CD_ + k0) * R_);
            float4* dst = (float4*)Bs;
            dst[tid]       = src[tid];
            dst[tid + 256] = src[tid + 256];
            dst[tid + 512] = src[tid + 512];
            dst[tid + 768] = src[tid + 768];
        }
        __syncthreads();
        mmcore<4>(As, 132, Bs, 64, i0, j0, 64, acc);
    }
    __syncthreads();
#pragma unroll
    for (int jj = 0; jj < 4; ++jj)
#pragma unroll
        for (int ip = 0; ip < 4; ++ip) {
            L[(j0 + jj) * 129 + (i0 + 2 * ip)]     = lo2(acc[jj][ip]);
            L[(j0 + jj) * 129 + (i0 + 2 * ip + 1)] = hi2(acc[jj][ip]);
        }
    __syncthreads();
    if (tid < 128) {
        const float scale = 0.022097086912079608f;
        const float NEG_INF = __int_as_float(0xff800000);
        int n = n0 + tid;
        int nc = (n > NP_ - 1) ? NP_ - 1 : n;
        int mi = rowI[nc], mj = colI[nc];
        float m = NEG_INF;
#pragma unroll 8
        for (int r = 0; r < 64; ++r) {
            float v = L[r * 129 + tid] * scale;
            if (r == mi || r == mj) v = NEG_INF;
            m = fmaxf(m, v);
        }
        float ssum = 0.f;
#pragma unroll 8
        for (int r = 0; r < 64; ++r) {
            float v = L[r * 129 + tid] * scale;
            if (r == mi || r == mj) v = NEG_INF;
            float e = __expf(v - m);
            ssum += e;
            L[r * 129 + tid] = e;
        }
        float inv = 1.f / ssum;
        if (n < NP_) {
            float* dst = g_aT + (size_t)b * R_ * NP_ + n;
#pragma unroll 8
            for (int r = 0; r < 64; ++r) dst[(size_t)r * NP_] = L[r * 129 + tid] * inv;
        }
    }
}

// ============ K4: x_glob = alpha @ batch_input  (SIMT) ============
__global__ void __launch_bounds__(256) k4_xglob(const float* __restrict__ bi) {
    extern __shared__ float sm[];
    float* As = sm;
    float* Bs = sm + 64 * 132;
    int b = blockIdx.x >> 8;
    int rest = blockIdx.x & 255;
    int n0 = (rest >> 4) * 128;
    int cd0 = (rest & 15) * 128;
    int tid = threadIdx.x;
    int i0 = (tid >> 4) * 8, j0 = (tid & 15) * 8;
    {
        int row = tid & 63, part = tid >> 6;
        const float* arow = g_aT + ((size_t)b * R_ + row) * NP_;
#pragma unroll
        for (int f = 0; f < 8; ++f) {
            int col = (part * 8 + f) * 4;
            int srcc = n0 + col;
            if (srcc > NP_ - 4) srcc = NP_ - 4;
            float4 v = *(const float4*)(arow + srcc);
            *(float4*)(As + row * 132 + col) = v;
        }
        const float4* brow = (const float4*)(bi + ((size_t)b * R_ + row) * CD_ + cd0);
        float4* bsr = (float4*)(Bs + row * 128);
#pragma unroll
        for (int f = 0; f < 8; ++f) bsr[part * 8 + f] = brow[part * 8 + f];
    }
    __syncthreads();
    unsigned long long acc[8][4];
    ZERO_ACC(acc, 8)
    mmcore<8>(As, 132, Bs, 128, i0, j0, 64, acc);
#pragma unroll
    for (int ip = 0; ip < 4; ++ip)
#pragma unroll
        for (int s = 0; s < 2; ++s) {
            int n = n0 + i0 + 2 * ip + s;
            if (n < NP_) {
                float o[8];
#pragma unroll
                for (int jj = 0; jj < 8; ++jj)
                    o[jj] = s ? hi2(acc[jj][ip]) : lo2(acc[jj][ip]);
                float4* dst = (float4*)(g_xg + ((size_t)(b * NP_) + n) * CD_ + cd0 + j0);
                dst[0] = make_float4(o[0], o[1], o[2], o[3]);
                dst[1] = make_float4(o[4], o[5], o[6], o[7]);
            }
        }
}

// ============ K5 (HMMA): gGEMM -> gate mix -> s1GEMM -> gelu.s2 -> masked sum ============
__global__ void __launch_bounds__(256) k5_mma(const float* __restrict__ gb,
                                              const float* __restrict__ s1b,
                                              const float* __restrict__ s2W,
                                              const float* __restrict__ s2b,
                                              const float* __restrict__ seqm,
                                              float* __restrict__ out) {
    extern __shared__ __align__(16) char smem[];
    uint32_t sbase = smem_u32(smem);
    int tid = threadIdx.x, wid = tid >> 5, lane = tid & 31;
    int b = blockIdx.x / 252, p0 = (blockIdx.x % 252) * 8;
    int mbase = (wid & 3) * 32, nbase = (wid >> 2) * 64;

    wcopy(smem, 2, tid);   // gW
    // A = xg, split -> images
    {
        int row = tid >> 1, half = tid & 1;
        int p = row >> 4, c = row & 15;
        const float4* s4 = (const float4*)(g_xg + ((size_t)(b * NP_) + p0 + p) * CD_
                                           + c * D_ + half * 64);
        char* arow = smem + row * ASTR + half * 128;
#pragma unroll
        for (int g = 0; g < 8; ++g) {
            float4 v0 = s4[2 * g], v1 = s4[2 * g + 1];
            uint4 h4, l4;
            split2(v0.x, v0.y, h4.x, l4.x);
            split2(v0.z, v0.w, h4.y, l4.y);
            split2(v1.x, v1.y, h4.z, l4.z);
            split2(v1.z, v1.w, h4.w, l4.w);
            *(uint4*)(arow + A_HI + g * 16) = h4;
            *(uint4*)(arow + A_LO + g * 16) = l4;
        }
    }
    __syncthreads();
    float c[2][8][4];
    gemm_hmma(sbase, mbase, nbase, lane, c);
    __syncthreads();
    // epilogue 1: xf = x + sigmoid(g+gb)*(xg-x) -> rebuild A images
#pragma unroll
    for (int mt = 0; mt < 2; ++mt)
#pragma unroll
        for (int ro = 0; ro < 2; ++ro) {
            int row = mbase + mt * 16 + ro * 8 + (lane >> 2);
            int p = row >> 4, cc = row & 15, n = p0 + p;
            const float* xb  = g_x  + ((size_t)(b * NP_) + n) * CD_ + cc * D_;
            const float* xgb = g_xg + ((size_t)(b * NP_) + n) * CD_ + cc * D_;
            char* arow = smem + row * ASTR;
#pragma unroll
            for (int nt = 0; nt < 8; ++nt) {
                int col = nbase + nt * 8 + (lane & 3) * 2;
                float2 vx = *(const float2*)(xb + col);
                float2 vg = *(const float2*)(xgb + col);
                float2 gbv = *(const float2*)(gb + col);
                float w0 = sigmoid_fast(c[mt][nt][ro * 2 + 0] + gbv.x);
                float w1 = sigmoid_fast(c[mt][nt][ro * 2 + 1] + gbv.y);
                float f0 = vx.x + w0 * (vg.x - vx.x);
                float f1 = vx.y + w1 * (vg.y - vx.y);
                unsigned hreg, lreg;
                split2(f0, f1, hreg, lreg);
                *(unsigned*)(arow + A_HI + col * 2) = hreg;
                *(unsigned*)(arow + A_LO + col * 2) = lreg;
            }
        }
    wcopy(smem, 3, tid);   // s1W
    __syncthreads();
    gemm_hmma(sbase, mbase, nbase, lane, c);
    __syncthreads();   // done reading A/W; reuse smem front for reductions
    float* red = (float*)smem;          // [128][2]
    float* srow = (float*)smem + 256;   // [128]
    // epilogue 2: gelu(u)·s2W dot per row
#pragma unroll
    for (int mt = 0; mt < 2; ++mt)
#pragma unroll
        for (int ro = 0; ro < 2; ++ro) {
            int row = mbase + mt * 16 + ro * 8 + (lane >> 2);
            float pr = 0.f;
#pragma unroll
            for (int nt = 0; nt < 8; ++nt) {
                int col = nbase + nt * 8 + (lane & 3) * 2;
                float2 sbv = *(const float2*)(s1b + col);
                float2 wv = *(const float2*)(s2W + col);
                pr += gelu_exact(c[mt][nt][ro * 2 + 0] + sbv.x) * wv.x;
                pr += gelu_exact(c[mt][nt][ro * 2 + 1] + sbv.y) * wv.y;
            }
            pr += __shfl_xor_sync(0xffffffffu, pr, 1);
            pr += __shfl_xor_sync(0xffffffffu, pr, 2);
            if ((lane & 3) == 0) red[row * 2 + (wid >> 2)] = pr;
        }
    __syncthreads();
    if (tid < 128) {
        float v = (red[tid * 2] + red[tid * 2 + 1] + s2b[0]) * seqm[b * C_ + (tid & 15)];
        srow[tid] = v;
    }
    __syncthreads();
    if (tid < 8) {
        float s = 0.f;
#pragma unroll
        for (int cc = 0; cc < 16; ++cc) s += srow[tid * 16 + cc];
        out[(size_t)b * NP_ + p0 + tid] = s;
    }
}

extern "C" void kernel_launch(void* const* d_in, const int* in_sizes, int n_in,
                              void* d_out, int out_size) {
    const float* bi   = (const float*)d_in[0];
    const float* seqm = (const float*)d_in[1];
    const int* rowI   = (const int*)d_in[2];
    const int* colI   = (const int*)d_in[3];
    const float* hW = (const float*)d_in[4];
    const float* hb = (const float*)d_in[5];
    const float* gW = (const float*)d_in[6];
    const float* gb = (const float*)d_in[7];
    const float* qW = (const float*)d_in[8];
    const float* qb = (const float*)d_in[9];
    const float* kW = (const float*)d_in[10];
    const float* kb = (const float*)d_in[11];
    const float* s1W = (const float*)d_in[12];
    const float* s1b = (const float*)d_in[13];
    const float* s2W = (const float*)d_in[14];
    const float* s2b = (const float*)d_in[15];
    float* out = (float*)d_out;

    cudaFuncSetAttribute(k1_kproj, cudaFuncAttributeMaxDynamicSharedMemorySize, SM1_);
    cudaFuncSetAttribute(k2_mma,   cudaFuncAttributeMaxDynamicSharedMemorySize, HSM_);
    cudaFuncSetAttribute(k3_alpha, cudaFuncAttributeMaxDynamicSharedMemorySize, SM3_);
    cudaFuncSetAttribute(k4_xglob, cudaFuncAttributeMaxDynamicSharedMemorySize, SM4_);
    cudaFuncSetAttribute(k5_mma,   cudaFuncAttributeMaxDynamicSharedMemorySize, HSM_);

    wprep<<<4, 256>>>(hW, qW, gW, s1W);
    k1_kproj<<<64, 256, SM1_>>>(bi, kW, kb);
    k2_mma<<<2016, 256, HSM_>>>(bi, rowI, colI, hb, qb);
    k3_alpha<<<128, 256, SM3_>>>(rowI, colI);
    k4_xglob<<<2048, 256, SM4_>>>(bi);
    k5_mma<<<2016, 256, HSM_>>>(gb, s1b, s2W, s2b, seqm, out);
}

// round 17
// speedup vs baseline: 2.8711x; 1.0698x over previous
#include <cuda_runtime.h>
#include <cuda_bf16.h>
#include <stdint.h>
#include <cstdint>
#include <math.h>

#define B_  8
#define R_  64
#define C_  16
#define D_  128
#define NP_ 2016
#define CD_ 2048

// ---- scratch (static device globals) ----
__device__ float g_x [(size_t)B_ * NP_ * CD_];   // x (gated pair features) fp32
__device__ float g_xg[(size_t)B_ * NP_ * CD_];   // x_glob fp32
// bf16 hi/lo images, row-major over last dim, 16B-aligned rows:
__device__ uint4 g_qh[(size_t)B_ * NP_ * 256];   // q  [b][n][2048]  (66 MB)
__device__ uint4 g_ql[(size_t)B_ * NP_ * 256];
__device__ uint4 g_kh[(size_t)B_ * R_ * 256];    // k  [b][r][2048]
__device__ uint4 g_kl[(size_t)B_ * R_ * 256];
__device__ uint4 g_ah[(size_t)B_ * 2048 * 8];    // alpha [b][n(pad2048)][64]
__device__ uint4 g_al[(size_t)B_ * 2048 * 8];
__device__ uint4 g_bh[(size_t)B_ * 2048 * 8];    // biT   [b][cd][64]
__device__ uint4 g_bl[(size_t)B_ * 2048 * 8];
// pre-built weight images row-major [n][k]: [0]=hW [1]=qW [2]=gW [3]=s1W
__device__ uint4 g_wh[4][2048];
__device__ uint4 g_wl[4][2048];

// ---- packed fp32x2 helpers (SIMT k1) ----
__device__ __forceinline__ unsigned long long fma2(unsigned long long a,
                                                   unsigned long long b,
                                                   unsigned long long c) {
    unsigned long long r;
    asm("fma.rn.f32x2 %0, %1, %2, %3;" : "=l"(r) : "l"(a), "l"(b), "l"(c));
    return r;
}
__device__ __forceinline__ unsigned long long pack2(float x) {
    unsigned long long r;
    unsigned u = __float_as_uint(x);
    asm("mov.b64 %0, {%1, %1};" : "=l"(r) : "r"(u));
    return r;
}
__device__ __forceinline__ float lo2(unsigned long long a) { return __uint_as_float((unsigned)a); }
__device__ __forceinline__ float hi2(unsigned long long a) { return __uint_as_float((unsigned)(a >> 32)); }

__device__ __forceinline__ float sigmoid_fast(float x) { return 1.f / (1.f + __expf(-x)); }
__device__ __forceinline__ float gelu_exact(float x) {
    return 0.5f * x * (1.f + erff(x * 0.70710678118654752f));
}

// ================= SIMT register-tiled GEMM core (k1) =================
template <int JJ>
__device__ __forceinline__ void mmcore(const float* As, int ALD,
                                       const float* Bs, int BLD,
                                       int i0, int j0, int K,
                                       unsigned long long acc[][4]) {
#pragma unroll 4
    for (int k = 0; k < K; ++k) {
        const ulonglong2* ap = (const ulonglong2*)(As + k * ALD + i0);
        ulonglong2 a01 = ap[0];
        ulonglong2 a23 = ap[1];
        const float4* bp = (const float4*)(Bs + k * BLD + j0);
        float bv[JJ];
        float4 b0 = bp[0];
        bv[0] = b0.x; bv[1] = b0.y; bv[2] = b0.z; bv[3] = b0.w;
        if (JJ == 8) {
            float4 b1 = bp[1];
            bv[4] = b1.x; bv[5] = b1.y; bv[6] = b1.z; bv[7] = b1.w;
        }
#pragma unroll
        for (int jj = 0; jj < JJ; ++jj) {
            unsigned long long b2 = pack2(bv[jj]);
            acc[jj][0] = fma2(a01.x, b2, acc[jj][0]);
            acc[jj][1] = fma2(a01.y, b2, acc[jj][1]);
            acc[jj][2] = fma2(a23.x, b2, acc[jj][2]);
            acc[jj][3] = fma2(a23.y, b2, acc[jj][3]);
        }
    }
}

#define ZERO_ACC(acc, JJ)                                          \
    _Pragma("unroll") for (int jj = 0; jj < JJ; ++jj)              \
        _Pragma("unroll") for (int ip = 0; ip < 4; ++ip) acc[jj][ip] = 0ull;

#define SM1_ ((128 * 132 + 128 * 128) * 4)

// ================= HMMA (mma.sync) infrastructure =================
__device__ __forceinline__ uint32_t smem_u32(const void* p) {
    uint32_t a;
    asm("{ .reg .u64 t; cvta.to.shared.u64 t, %1; cvt.u32.u64 %0, t; }" : "=r"(a) : "l"(p));
    return a;
}
__device__ __forceinline__ void ldm4(uint32_t addr, unsigned r[4]) {
    asm volatile("ldmatrix.sync.aligned.m8n8.x4.shared.b16 {%0,%1,%2,%3}, [%4];"
        : "=r"(r[0]), "=r"(r[1]), "=r"(r[2]), "=r"(r[3]) : "r"(addr));
}
__device__ __forceinline__ void mma16816(float c[4], const unsigned a[4],
                                         unsigned b0, unsigned b1) {
    asm volatile("mma.sync.aligned.m16n8k16.row.col.f32.bf16.bf16.f32 "
        "{%0,%1,%2,%3}, {%4,%5,%6,%7}, {%8,%9}, {%0,%1,%2,%3};"
        : "+f"(c[0]), "+f"(c[1]), "+f"(c[2]), "+f"(c[3])
        : "r"(a[0]), "r"(a[1]), "r"(a[2]), "r"(a[3]), "r"(b0), "r"(b1));
}

// fp32 -> (hi,lo) bf16x2 split for two values
__device__ __forceinline__ void split2(float a, float b, unsigned& h, unsigned& l) {
    __nv_bfloat162 hv = __floats2bfloat162_rn(a, b);
    float2 hf = __bfloat1622float2(hv);
    __nv_bfloat162 lv = __floats2bfloat162_rn(a - hf.x, b - hf.y);
    h = *reinterpret_cast<unsigned*>(&hv);
    l = *reinterpret_cast<unsigned*>(&lv);
}

// k2/k5 image layout: 128 rows x 272B stride
#define ASTR 272
#define IMG_ (128 * ASTR)
#define A_HI 0
#define A_LO IMG_
#define W_HI (2 * IMG_)
#define W_LO (3 * IMG_)
#define HSM_ (4 * IMG_)

// 3-term split HMMA GEMM (k2/k5): c += Ahi*Whi + Ahi*Wlo + Alo*Whi
__device__ __forceinline__ void gemm_hmma(uint32_t sbase, int mbase, int nbase,
                                          int lane, float c[2][8][4]) {
#pragma unroll
    for (int mt = 0; mt < 2; ++mt)
#pragma unroll
        for (int nt = 0; nt < 8; ++nt)
#pragma unroll
            for (int i = 0; i < 4; ++i) c[mt][nt][i] = 0.f;
    int lrow = lane & 15, lhi = (lane >> 4) * 16;
#pragma unroll
    for (int kc = 0; kc < 8; ++kc) {
        unsigned ah[2][4], al[2][4];
#pragma unroll
        for (int mt = 0; mt < 2; ++mt) {
            uint32_t ra = sbase + (mbase + mt * 16 + lrow) * ASTR + kc * 32 + lhi;
            ldm4(ra + A_HI, ah[mt]);
            ldm4(ra + A_LO, al[mt]);
        }
        unsigned bh[4][4], bl[4][4];
#pragma unroll
        for (int np = 0; np < 4; ++np) {
            uint32_t rb = sbase + (nbase + np * 16 + lrow) * ASTR + kc * 32 + lhi;
            ldm4(rb + W_HI, bh[np]);
            ldm4(rb + W_LO, bl[np]);
        }
#pragma unroll
        for (int mt = 0; mt < 2; ++mt)
#pragma unroll
            for (int np = 0; np < 4; ++np) {
                mma16816(c[mt][2 * np],     ah[mt], bh[np][0], bh[np][2]);
                mma16816(c[mt][2 * np + 1], ah[mt], bh[np][1], bh[np][3]);
                mma16816(c[mt][2 * np],     ah[mt], bl[np][0], bl[np][2]);
                mma16816(c[mt][2 * np + 1], ah[mt], bl[np][1], bl[np][3]);
                mma16816(c[mt][2 * np],     al[mt], bh[np][0], bh[np][2]);
                mma16816(c[mt][2 * np + 1], al[mt], bh[np][1], bh[np][3]);
            }
    }
}

__device__ __forceinline__ void wcopy(char* smem, int w, int tid) {
    const uint4* sh = g_wh[w];
    const uint4* sl = g_wl[w];
    for (int i = tid; i < 2048; i += 256) {
        int row = i >> 4, seg = i & 15;
        *(uint4*)(smem + W_HI + row * ASTR + seg * 16) = sh[i];
        *(uint4*)(smem + W_LO + row * ASTR + seg * 16) = sl[i];
    }
}

// ============ W prep: bf16 hi/lo weight images, row-major [n][k] ============
__global__ void __launch_bounds__(256) wprep(const float* __restrict__ hW,
                                             const float* __restrict__ qW,
                                             const float* __restrict__ gW,
                                             const float* __restrict__ s1W) {
    const float* Ws[4] = {hW, qW, gW, s1W};
    int w = blockIdx.x;
    const float* W = Ws[w];
    char* dh = (char*)&g_wh[w][0];
    char* dl = (char*)&g_wl[w][0];
    for (int e = threadIdx.x; e < 16384; e += blockDim.x) {
        int n = e >> 7, k = e & 127;
        float v = W[k * 128 + n];
        __nv_bfloat16 h = __float2bfloat16(v);
        float r = v - __bfloat162float(h);
        __nv_bfloat16 l = __float2bfloat16(r);
        *(__nv_bfloat16*)(dh + n * 256 + k * 2) = h;
        *(__nv_bfloat16*)(dl + n * 256 + k * 2) = l;
    }
}

// ============ W prep 2: biT bf16 hi/lo images [b][cd][64 r] ============
__global__ void __launch_bounds__(256) wprep2(const float* __restrict__ bi) {
    __shared__ float sm[64 * 132];
    int tid = threadIdx.x;
    int b = blockIdx.x >> 4;
    int cd0 = (blockIdx.x & 15) * 128;
    for (int i = tid; i < 64 * 32; i += 256) {
        int r = i >> 5, seg = i & 31;
        *(float4*)(sm + r * 132 + seg * 4) =
            *(const float4*)(bi + ((size_t)(b * R_ + r)) * CD_ + cd0 + seg * 4);
    }
    __syncthreads();
    if (tid < 128) {
        size_t base = ((size_t)(b * 2048 + cd0 + tid)) * 32;
#pragma unroll 8
        for (int rr = 0; rr < 32; ++rr) {
            float a0 = sm[(2 * rr) * 132 + tid];
            float a1 = sm[(2 * rr + 1) * 132 + tid];
            unsigned h, l;
            split2(a0, a1, h, l);
            ((unsigned*)g_bh)[base + rr] = h;
            ((unsigned*)g_bl)[base + rr] = l;
        }
    }
}

// ============ K1: k-projection -> bf16 hi/lo images [b][r][cd] (SIMT GEMM) ============
__global__ void __launch_bounds__(256) k1_kproj(const float* __restrict__ bi,
                                                const float* __restrict__ kW,
                                                const float* __restrict__ kb) {
    extern __shared__ float sm[];
    float* As = sm;
    float* Bs = sm + 128 * 132;
    int tid = threadIdx.x;
    int i0 = (tid >> 4) * 8, j0 = (tid & 15) * 8;
    int lrow = tid & 127, lhalf = tid >> 7;
    int row0 = blockIdx.x * 128;
    {
        const float4* in4 = (const float4*)(bi + (size_t)(row0 + lrow) * D_);
#pragma unroll
        for (int f = 0; f < 16; ++f) {
            int d4 = lhalf * 16 + f;
            float4 v = in4[d4];
            int k = d4 * 4;
            As[(k + 0) * 132 + lrow] = v.x;
            As[(k + 1) * 132 + lrow] = v.y;
            As[(k + 2) * 132 + lrow] = v.z;
            As[(k + 3) * 132 + lrow] = v.w;
        }
        const float4* w4 = (const float4*)kW;
        float4* bs4 = (float4*)Bs;
#pragma unroll
        for (int f = 0; f < 16; ++f) bs4[tid + 256 * f] = w4[tid + 256 * f];
    }
    __syncthreads();
    unsigned long long acc[8][4];
    ZERO_ACC(acc, 8)
    mmcore<8>(As, 132, Bs, 128, i0, j0, 128, acc);
    float kbv[8];
    {
        const float4* b4 = (const float4*)(kb + j0);
        float4 t0 = b4[0], t1 = b4[1];
        kbv[0] = t0.x; kbv[1] = t0.y; kbv[2] = t0.z; kbv[3] = t0.w;
        kbv[4] = t1.x; kbv[5] = t1.y; kbv[6] = t1.z; kbv[7] = t1.w;
    }
#pragma unroll
    for (int ip = 0; ip < 4; ++ip)
#pragma unroll
        for (int s = 0; s < 2; ++s) {
            int grow = row0 + i0 + 2 * ip + s;
            int bb = grow >> 10;
            int r = (grow >> 4) & 63;
            int cc = grow & 15;
            float v[8];
#pragma unroll
            for (int jj = 0; jj < 8; ++jj)
                v[jj] = (s ? hi2(acc[jj][ip]) : lo2(acc[jj][ip])) + kbv[jj];
            uint4 hq, lq;
            split2(v[0], v[1], hq.x, lq.x);
            split2(v[2], v[3], hq.y, lq.y);
            split2(v[4], v[5], hq.z, lq.z);
            split2(v[6], v[7], hq.w, lq.w);
            size_t idx = ((size_t)(bb * R_ + r)) * 256 + (cc * 128 + j0) / 8;
            g_kh[idx] = hq;
            g_kl[idx] = lq;
        }
}

// ============ K2 (HMMA): diff -> hGEMM -> gate -> x -> qGEMM -> q images ============
__global__ void __launch_bounds__(256) k2_mma(const float* __restrict__ bi,
                                              const int* __restrict__ rowI,
                                              const int* __restrict__ colI,
                                              const float* __restrict__ hb,
                                              const float* __restrict__ qb) {
    extern __shared__ __align__(16) char smem[];
    uint32_t sbase = smem_u32(smem);
    int tid = threadIdx.x, wid = tid >> 5, lane = tid & 31;
    int b = blockIdx.x / 252, p0 = (blockIdx.x % 252) * 8;
    int mbase = (wid & 3) * 32, nbase = (wid >> 2) * 64;

    wcopy(smem, 0, tid);   // hW
    {
        int row = tid >> 1, half = tid & 1;
        int p = row >> 4, c = row & 15;
        int ri = rowI[p0 + p], rj = colI[p0 + p];
        const float4* xi4 = (const float4*)(bi + (((size_t)b * R_ + ri) * C_ + c) * D_ + half * 64);
        const float4* xj4 = (const float4*)(bi + (((size_t)b * R_ + rj) * C_ + c) * D_ + half * 64);
        char* arow = smem + row * ASTR + half * 128;
#pragma unroll
        for (int g = 0; g < 8; ++g) {
            float4 a0 = xi4[2 * g], a1 = xi4[2 * g + 1];
            float4 b0 = xj4[2 * g], b1 = xj4[2 * g + 1];
            uint4 h4, l4;
            split2(a0.x - b0.x, a0.y - b0.y, h4.x, l4.x);
            split2(a0.z - b0.z, a0.w - b0.w, h4.y, l4.y);
            split2(a1.x - b1.x, a1.y - b1.y, h4.z, l4.z);
            split2(a1.z - b1.z, a1.w - b1.w, h4.w, l4.w);
            *(uint4*)(arow + A_HI + g * 16) = h4;
            *(uint4*)(arow + A_LO + g * 16) = l4;
        }
    }
    __syncthreads();
    float c[2][8][4];
    gemm_hmma(sbase, mbase, nbase, lane, c);
    __syncthreads();
    // epilogue 1: x = xj + sigmoid(h+hb)*(xi-xj); store g_x fp32 + rebuild A images
#pragma unroll
    for (int mt = 0; mt < 2; ++mt)
#pragma unroll
        for (int ro = 0; ro < 2; ++ro) {
            int row = mbase + mt * 16 + ro * 8 + (lane >> 2);
            int p = row >> 4, cc = row & 15, n = p0 + p;
            int ri = rowI[n], rj = colI[n];
            const float* xib = bi + (((size_t)b * R_ + ri) * C_ + cc) * D_;
            const float* xjb = bi + (((size_t)b * R_ + rj) * C_ + cc) * D_;
            float* xo = g_x + ((size_t)(b * NP_) + n) * CD_ + cc * D_;
            char* arow = smem + row * ASTR;
#pragma unroll
            for (int nt = 0; nt < 8; ++nt) {
                int col = nbase + nt * 8 + (lane & 3) * 2;
                float2 vi = *(const float2*)(xib + col);
                float2 vj = *(const float2*)(xjb + col);
                float2 hbv = *(const float2*)(hb + col);
                float h0 = c[mt][nt][ro * 2 + 0] + hbv.x;
                float h1 = c[mt][nt][ro * 2 + 1] + hbv.y;
                float x0 = vj.x + sigmoid_fast(h0) * (vi.x - vj.x);
                float x1 = vj.y + sigmoid_fast(h1) * (vi.y - vj.y);
                *(float2*)(xo + col) = make_float2(x0, x1);
                unsigned hreg, lreg;
                split2(x0, x1, hreg, lreg);
                *(unsigned*)(arow + A_HI + col * 2) = hreg;
                *(unsigned*)(arow + A_LO + col * 2) = lreg;
            }
        }
    wcopy(smem, 1, tid);   // qW
    __syncthreads();
    gemm_hmma(sbase, mbase, nbase, lane, c);
    // epilogue 2: q = c + qb -> bf16 hi/lo images
#pragma unroll
    for (int mt = 0; mt < 2; ++mt)
#pragma unroll
        for (int ro = 0; ro < 2; ++ro) {
            int row = mbase + mt * 16 + ro * 8 + (lane >> 2);
            int p = row >> 4, cc = row & 15, n = p0 + p;
            size_t qbase = ((size_t)(b * NP_) + n) * 1024;   // 1024 unsigned per row
#pragma unroll
            for (int nt = 0; nt < 8; ++nt) {
                int col = nbase + nt * 8 + (lane & 3) * 2;
                float2 qbv = *(const float2*)(qb + col);
                float o0 = c[mt][nt][ro * 2 + 0] + qbv.x;
                float o1 = c[mt][nt][ro * 2 + 1] + qbv.y;
                unsigned h, l;
                split2(o0, o1, h, l);
                size_t off = qbase + (cc * 128 + col) / 2;
                ((unsigned*)g_qh)[off] = h;
                ((unsigned*)g_ql)[off] = l;
            }
        }
}

// ============ K3 (HMMA): logits = q @ k^T, masked softmax -> alpha images ============
#define K3QHI 0
#define K3QLO 34816
#define K3KHI 69632
#define K3KLO 87040
#define K3SM_ 104448
__global__ void __launch_bounds__(256) k3_mma(const int* __restrict__ rowI,
                                              const int* __restrict__ colI) {
    extern __shared__ __align__(16) char smem[];
    uint32_t sbase = smem_u32(smem);
    int tid = threadIdx.x, wid = tid >> 5, lane = tid & 31;
    int b = blockIdx.x >> 4;
    int n0 = (blockIdx.x & 15) * 128;
    int mbase = (wid & 3) * 32, nbase = (wid >> 2) * 32;
    int lrow = lane & 15, lhi = (lane >> 4) * 16;
    float c[2][4][4];
#pragma unroll
    for (int mt = 0; mt < 2; ++mt)
#pragma unroll
        for (int rt = 0; rt < 4; ++rt)
#pragma unroll
            for (int e = 0; e < 4; ++e) c[mt][rt][e] = 0.f;

    for (int ch = 0; ch < 16; ++ch) {
        if (ch) __syncthreads();
        for (int i = tid; i < 2048; i += 256) {
            int row = i >> 4, seg = i & 15;
            int nsrc = n0 + row;
            if (nsrc > NP_ - 1) nsrc = NP_ - 1;
            size_t s = ((size_t)(b * NP_ + nsrc)) * 256 + ch * 16 + seg;
            *(uint4*)(smem + K3QHI + row * ASTR + seg * 16) = g_qh[s];
            *(uint4*)(smem + K3QLO + row * ASTR + seg * 16) = g_ql[s];
        }
        for (int i = tid; i < 1024; i += 256) {
            int row = i >> 4, seg = i & 15;
            size_t s = ((size_t)(b * R_ + row)) * 256 + ch * 16 + seg;
            *(uint4*)(smem + K3KHI + row * ASTR + seg * 16) = g_kh[s];
            *(uint4*)(smem + K3KLO + row * ASTR + seg * 16) = g_kl[s];
        }
        __syncthreads();
#pragma unroll
        for (int kc = 0; kc < 8; ++kc) {
            unsigned ah[2][4], al[2][4], bh[2][4], bl[2][4];
#pragma unroll
            for (int mt = 0; mt < 2; ++mt) {
                uint32_t ra = sbase + K3QHI + (mbase + mt * 16 + lrow) * ASTR + kc * 32 + lhi;
                ldm4(ra, ah[mt]);
                ldm4(ra + (K3QLO - K3QHI), al[mt]);
            }
#pragma unroll
            for (int np = 0; np < 2; ++np) {
                uint32_t rb = sbase + K3KHI + (nbase + np * 16 + lrow) * ASTR + kc * 32 + lhi;
                ldm4(rb, bh[np]);
                ldm4(rb + (K3KLO - K3KHI), bl[np]);
            }
#pragma unroll
            for (int mt = 0; mt < 2; ++mt)
#pragma unroll
                for (int np = 0; np < 2; ++np) {
                    mma16816(c[mt][2 * np],     ah[mt], bh[np][0], bh[np][2]);
                    mma16816(c[mt][2 * np + 1], ah[mt], bh[np][1], bh[np][3]);
                    mma16816(c[mt][2 * np],     ah[mt], bl[np][0], bl[np][2]);
                    mma16816(c[mt][2 * np + 1], ah[mt], bl[np][1], bl[np][3]);
                    mma16816(c[mt][2 * np],     al[mt], bh[np][0], bh[np][2]);
                    mma16816(c[mt][2 * np + 1], al[mt], bh[np][1], bh[np][3]);
                }
        }
    }
    __syncthreads();
    // logits -> smem overlay L[128][68]
    float* L = (float*)smem;
#pragma unroll
    for (int mt = 0; mt < 2; ++mt)
#pragma unroll
        for (int rt = 0; rt < 4; ++rt)
#pragma unroll
            for (int e = 0; e < 4; ++e) {
                int row = mbase + mt * 16 + (lane >> 2) + (e >> 1) * 8;
                int col = nbase + rt * 8 + (lane & 3) * 2 + (e & 1);
                L[row * 68 + col] = c[mt][rt][e];
            }
    __syncthreads();
    if (tid < 128) {
        int n = n0 + tid;
        if (n < NP_) {
            const float scale = 0.022097086912079608f;   // 1/sqrt(D*C)
            const float NEG_INF = __int_as_float(0xff800000);
            int mi = rowI[n], mj = colI[n];
            float* Lr = L + tid * 68;
            float m = NEG_INF;
#pragma unroll 8
            for (int r = 0; r < 64; ++r) {
                float v = Lr[r] * scale;
                if (r == mi || r == mj) v = NEG_INF;
                m = fmaxf(m, v);
            }
            float ssum = 0.f;
#pragma unroll 8
            for (int r = 0; r < 64; ++r) {
                float v = Lr[r] * scale;
                if (r == mi || r == mj) v = NEG_INF;
                float e = __expf(v - m);
                ssum += e;
                Lr[r] = e;
            }
            float inv = 1.f / ssum;
            size_t base = ((size_t)(b * 2048 + n)) * 32;
#pragma unroll 8
            for (int rr = 0; rr < 32; ++rr) {
                float a0 = Lr[2 * rr] * inv;
                float a1 = Lr[2 * rr + 1] * inv;
                unsigned h, l;
                split2(a0, a1, h, l);
                ((unsigned*)g_ah)[base + rr] = h;
                ((unsigned*)g_al)[base + rr] = l;
            }
        }
    }
}

// ============ K4 (HMMA): x_glob = alpha @ bi ============
#define K4STR 144
#define K4AHI 0
#define K4ALO 18432
#define K4BHI 36864
#define K4BLO 55296
#define K4SM_ 73728
__global__ void __launch_bounds__(256) k4_mma() {
    extern __shared__ __align__(16) char smem[];
    uint32_t sbase = smem_u32(smem);
    int tid = threadIdx.x, wid = tid >> 5, lane = tid & 31;
    int b = blockIdx.x >> 8;
    int rest = blockIdx.x & 255;
    int n0 = (rest >> 4) * 128;
    int cd0 = (rest & 15) * 128;
    int mbase = (wid & 3) * 32, nbase = (wid >> 2) * 64;
    for (int i = tid; i < 1024; i += 256) {
        int row = i >> 3, seg = i & 7;
        int nsrc = n0 + row;
        if (nsrc > NP_ - 1) nsrc = NP_ - 1;
        size_t sa = ((size_t)(b * 2048 + nsrc)) * 8 + seg;
        *(uint4*)(smem + K4AHI + row * K4STR + seg * 16) = g_ah[sa];
        *(uint4*)(smem + K4ALO + row * K4STR + seg * 16) = g_al[sa];
        size_t sb = ((size_t)(b * 2048 + cd0 + row)) * 8 + seg;
        *(uint4*)(smem + K4BHI + row * K4STR + seg * 16) = g_bh[sb];
        *(uint4*)(smem + K4BLO + row * K4STR + seg * 16) = g_bl[sb];
    }
    __syncthreads();
    int lrow = lane & 15, lhi = (lane >> 4) * 16;
    float c[2][8][4];
#pragma unroll
    for (int mt = 0; mt < 2; ++mt)
#pragma unroll
        for (int nt = 0; nt < 8; ++nt)
#pragma unroll
            for (int e = 0; e < 4; ++e) c[mt][nt][e] = 0.f;
#pragma unroll
    for (int kc = 0; kc < 4; ++kc) {
        unsigned ah[2][4], al[2][4], bh[4][4], bl[4][4];
#pragma unroll
        for (int mt = 0; mt < 2; ++mt) {
            uint32_t ra = sbase + K4AHI + (mbase + mt * 16 + lrow) * K4STR + kc * 32 + lhi;
            ldm4(ra, ah[mt]);
            ldm4(ra + (K4ALO - K4AHI), al[mt]);
        }
#pragma unroll
        for (int np = 0; np < 4; ++np) {
            uint32_t rb = sbase + K4BHI + (nbase + np * 16 + lrow) * K4STR + kc * 32 + lhi;
            ldm4(rb, bh[np]);
            ldm4(rb + (K4BLO - K4BHI), bl[np]);
        }
#pragma unroll
        for (int mt = 0; mt < 2; ++mt)
#pragma unroll
            for (int np = 0; np < 4; ++np) {
                mma16816(c[mt][2 * np],     ah[mt], bh[np][0], bh[np][2]);
                mma16816(c[mt][2 * np + 1], ah[mt], bh[np][1], bh[np][3]);
                mma16816(c[mt][2 * np],     ah[mt], bl[np][0], bl[np][2]);
                mma16816(c[mt][2 * np + 1], ah[mt], bl[np][1], bl[np][3]);
                mma16816(c[mt][2 * np],     al[mt], bh[np][0], bh[np][2]);
                mma16816(c[mt][2 * np + 1], al[mt], bh[np][1], bh[np][3]);
            }
    }
    // epilogue: write xg fp32
#pragma unroll
    for (int mt = 0; mt < 2; ++mt)
#pragma unroll
        for (int ro = 0; ro < 2; ++ro) {
            int rloc = mbase + mt * 16 + ro * 8 + (lane >> 2);
            int n = n0 + rloc;
            if (n < NP_) {
                float* xo = g_xg + ((size_t)(b * NP_) + n) * CD_ + cd0;
#pragma unroll
                for (int nt = 0; nt < 8; ++nt) {
                    int col = nbase + nt * 8 + (lane & 3) * 2;
                    *(float2*)(xo + col) = make_float2(c[mt][nt][ro * 2 + 0],
                                                       c[mt][nt][ro * 2 + 1]);
                }
            }
        }
}

// ============ K5 (HMMA): gGEMM -> gate mix -> s1GEMM -> gelu.s2 -> masked sum ============
__global__ void __launch_bounds__(256) k5_mma(const float* __restrict__ gb,
                                              const float* __restrict__ s1b,
                                              const float* __restrict__ s2W,
                                              const float* __restrict__ s2b,
                                              const float* __restrict__ seqm,
                                              float* __restrict__ out) {
    extern __shared__ __align__(16) char smem[];
    uint32_t sbase = smem_u32(smem);
    int tid = threadIdx.x, wid = tid >> 5, lane = tid & 31;
    int b = blockIdx.x / 252, p0 = (blockIdx.x % 252) * 8;
    int mbase = (wid & 3) * 32, nbase = (wid >> 2) * 64;

    wcopy(smem, 2, tid);   // gW
    {
        int row = tid >> 1, half = tid & 1;
        int p = row >> 4, c = row & 15;
        const float4* s4 = (const float4*)(g_xg + ((size_t)(b * NP_) + p0 + p) * CD_
                                           + c * D_ + half * 64);
        char* arow = smem + row * ASTR + half * 128;
#pragma unroll
        for (int g = 0; g < 8; ++g) {
            float4 v0 = s4[2 * g], v1 = s4[2 * g + 1];
            uint4 h4, l4;
            split2(v0.x, v0.y, h4.x, l4.x);
            split2(v0.z, v0.w, h4.y, l4.y);
            split2(v1.x, v1.y, h4.z, l4.z);
            split2(v1.z, v1.w, h4.w, l4.w);
            *(uint4*)(arow + A_HI + g * 16) = h4;
            *(uint4*)(arow + A_LO + g * 16) = l4;
        }
    }
    __syncthreads();
    float c[2][8][4];
    gemm_hmma(sbase, mbase, nbase, lane, c);
    __syncthreads();
#pragma unroll
    for (int mt = 0; mt < 2; ++mt)
#pragma unroll
        for (int ro = 0; ro < 2; ++ro) {
            int row = mbase + mt * 16 + ro * 8 + (lane >> 2);
            int p = row >> 4, cc = row & 15, n = p0 + p;
            const float* xb  = g_x  + ((size_t)(b * NP_) + n) * CD_ + cc * D_;
            const float* xgb = g_xg + ((size_t)(b * NP_) + n) * CD_ + cc * D_;
            char* arow = smem + row * ASTR;
#pragma unroll
            for (int nt = 0; nt < 8; ++nt) {
                int col = nbase + nt * 8 + (lane & 3) * 2;
                float2 vx = *(const float2*)(xb + col);
                float2 vg = *(const float2*)(xgb + col);
                float2 gbv = *(const float2*)(gb + col);
                float w0 = sigmoid_fast(c[mt][nt][ro * 2 + 0] + gbv.x);
                float w1 = sigmoid_fast(c[mt][nt][ro * 2 + 1] + gbv.y);
                float f0 = vx.x + w0 * (vg.x - vx.x);
                float f1 = vx.y + w1 * (vg.y - vx.y);
                unsigned hreg, lreg;
                split2(f0, f1, hreg, lreg);
                *(unsigned*)(arow + A_HI + col * 2) = hreg;
                *(unsigned*)(arow + A_LO + col * 2) = lreg;
            }
        }
    wcopy(smem, 3, tid);   // s1W
    __syncthreads();
    gemm_hmma(sbase, mbase, nbase, lane, c);
    __syncthreads();
    float* red = (float*)smem;          // [128][2]
    float* srow = (float*)smem + 256;   // [128]
#pragma unroll
    for (int mt = 0; mt < 2; ++mt)
#pragma unroll
        for (int ro = 0; ro < 2; ++ro) {
            int row = mbase + mt * 16 + ro * 8 + (lane >> 2);
            float pr = 0.f;
#pragma unroll
            for (int nt = 0; nt < 8; ++nt) {
                int col = nbase + nt * 8 + (lane & 3) * 2;
                float2 sbv = *(const float2*)(s1b + col);
                float2 wv = *(const float2*)(s2W + col);
                pr += gelu_exact(c[mt][nt][ro * 2 + 0] + sbv.x) * wv.x;
                pr += gelu_exact(c[mt][nt][ro * 2 + 1] + sbv.y) * wv.y;
            }
            pr += __shfl_xor_sync(0xffffffffu, pr, 1);
            pr += __shfl_xor_sync(0xffffffffu, pr, 2);
            if ((lane & 3) == 0) red[row * 2 + (wid >> 2)] = pr;
        }
    __syncthreads();
    if (tid < 128) {
        float v = (red[tid * 2] + red[tid * 2 + 1] + s2b[0]) * seqm[b * C_ + (tid & 15)];
        srow[tid] = v;
    }
    __syncthreads();
    if (tid < 8) {
        float s = 0.f;
#pragma unroll
        for (int cc = 0; cc < 16; ++cc) s += srow[tid * 16 + cc];
        out[(size_t)b * NP_ + p0 + tid] = s;
    }
}

extern "C" void kernel_launch(void* const* d_in, const int* in_sizes, int n_in,
                              void* d_out, int out_size) {
    const float* bi   = (const float*)d_in[0];
    const float* seqm = (const float*)d_in[1];
    const int* rowI   = (const int*)d_in[2];
    const int* colI   = (const int*)d_in[3];
    const float* hW = (const float*)d_in[4];
    const float* hb = (const float*)d_in[5];
    const float* gW = (const float*)d_in[6];
    const float* gb = (const float*)d_in[7];
    const float* qW = (const float*)d_in[8];
    const float* qb = (const float*)d_in[9];
    const float* kW = (const float*)d_in[10];
    const float* kb = (const float*)d_in[11];
    const float* s1W = (const float*)d_in[12];
    const float* s1b = (const float*)d_in[13];
    const float* s2W = (const float*)d_in[14];
    const float* s2b = (const float*)d_in[15];
    float* out = (float*)d_out;

    cudaFuncSetAttribute(k1_kproj, cudaFuncAttributeMaxDynamicSharedMemorySize, SM1_);
    cudaFuncSetAttribute(k2_mma,   cudaFuncAttributeMaxDynamicSharedMemorySize, HSM_);
    cudaFuncSetAttribute(k3_mma,   cudaFuncAttributeMaxDynamicSharedMemorySize, K3SM_);
    cudaFuncSetAttribute(k4_mma,   cudaFuncAttributeMaxDynamicSharedMemorySize, K4SM_);
    cudaFuncSetAttribute(k5_mma,   cudaFuncAttributeMaxDynamicSharedMemorySize, HSM_);

    wprep<<<4, 256>>>(hW, qW, gW, s1W);
    wprep2<<<128, 256>>>(bi);
    k1_kproj<<<64, 256, SM1_>>>(bi, kW, kb);
    k2_mma<<<2016, 256, HSM_>>>(bi, rowI, colI, hb, qb);
    k3_mma<<<128, 256, K3SM_>>>(rowI, colI);
    k4_mma<<<2048, 256, K4SM_>>>();
    k5_mma<<<2016, 256, HSM_>>>(gb, s1b, s2W, s2b, seqm, out);
}